// round 1
// baseline (speedup 1.0000x reference)
#include <cuda_runtime.h>
#include <math.h>

#define NNODES 50000
#define INCH   128
#define HID    128          // per-head channels of conv1 (= 2*OUT_CH)
#define OUTCH  64
#define E_REAL 400000
#define E_TOT  450000       // + self loops

// ---------------- scratch (device globals; no allocations allowed) ----------
__device__ __align__(16) float g_H1[(size_t)NNODES * 256];   // x @ W1
__device__ __align__(16) float g_O1[(size_t)NNODES * 256];   // elu(aggregated)
__device__ __align__(16) float g_H2[(size_t)NNODES * 128];   // [h@Wmu | h@Wls]
__device__ float g_as1[NNODES * 2], g_ad1[NNODES * 2];
__device__ float g_as2[NNODES * 2], g_ad2[NNODES * 2];
__device__ int   g_deg[NNODES + 1];
__device__ int   g_off[NNODES + 1];
__device__ int   g_cur[NNODES];
__device__ int   g_srcList[E_TOT];
__device__ float g_attS2[128], g_attD2[128];

// ---------------- small utility kernels -------------------------------------
__global__ void zero_int_kernel(int* p, int n) {
    int i = blockIdx.x * blockDim.x + threadIdx.x;
    if (i < n) p[i] = 0;
}

__global__ void copy_int_kernel(const int* __restrict__ a, int* __restrict__ b, int n) {
    int i = blockIdx.x * blockDim.x + threadIdx.x;
    if (i < n) b[i] = a[i];
}

// histogram of destination nodes (real edges + implicit self loops)
__global__ void hist_kernel(const int* __restrict__ ei, int* __restrict__ deg) {
    int i = blockIdx.x * blockDim.x + threadIdx.x;
    if (i >= E_TOT) return;
    int dst = (i < E_REAL) ? ei[E_REAL + i] : (i - E_REAL);
    atomicAdd(&deg[dst], 1);
}

// single-block exclusive scan over NNODES degrees
__global__ void scan_kernel(const int* __restrict__ deg, int* __restrict__ off, int n, int total) {
    __shared__ int warpSums[32];
    __shared__ int s_carry;
    int tid = threadIdx.x, lane = tid & 31, wid = tid >> 5;
    if (tid == 0) s_carry = 0;
    __syncthreads();
    for (int base = 0; base < n; base += 1024) {
        int idx = base + tid;
        int v = (idx < n) ? deg[idx] : 0;
        int x = v;
        #pragma unroll
        for (int o = 1; o < 32; o <<= 1) {
            int y = __shfl_up_sync(0xffffffffu, x, o);
            if (lane >= o) x += y;
        }
        if (lane == 31) warpSums[wid] = x;
        __syncthreads();
        if (wid == 0) {
            int w = warpSums[lane];
            #pragma unroll
            for (int o = 1; o < 32; o <<= 1) {
                int y = __shfl_up_sync(0xffffffffu, w, o);
                if (lane >= o) w += y;
            }
            warpSums[lane] = w;
        }
        __syncthreads();
        int blockIncl = x + (wid > 0 ? warpSums[wid - 1] : 0);
        int excl = blockIncl - v;
        if (idx < n) off[idx] = s_carry + excl;
        __syncthreads();
        if (tid == 1023) s_carry += blockIncl;
        __syncthreads();
    }
    if (tid == 0) off[n] = total;
}

// scatter edges into CSR-by-destination
__global__ void scatter_kernel(const int* __restrict__ ei, int* __restrict__ cur,
                               int* __restrict__ srcList) {
    int i = blockIdx.x * blockDim.x + threadIdx.x;
    if (i >= E_TOT) return;
    int src, dst;
    if (i < E_REAL) { src = ei[i]; dst = ei[E_REAL + i]; }
    else            { src = i - E_REAL; dst = src; }
    int p = atomicAdd(&cur[dst], 1);
    srcList[p] = src;
}

// pack layer-2 attention vectors: [mu | ls]
__global__ void pack_att_kernel(const float* smu, const float* sls,
                                const float* dmu, const float* dls,
                                float* S, float* D) {
    int i = threadIdx.x;  // 64
    S[i] = smu[i]; S[64 + i] = sls[i];
    D[i] = dmu[i]; D[64 + i] = dls[i];
}

// ---------------- GEMM: C[M,N] = A[M,K] @ B[K,N] (fp32, row-major) ----------
// BM=64 BN=64 BK=16, 256 threads, 4x4 per thread. K % 16 == 0, N % 64 == 0.
__global__ void gemm_kernel(const float* __restrict__ A, const float* __restrict__ B,
                            float* __restrict__ C, int M, int K, int N,
                            int ldc, int coff) {
    __shared__ float As[16][64 + 4];
    __shared__ float Bs[16][64];
    int t = threadIdx.x;
    int tx = t & 15, ty = t >> 4;
    int blockM = blockIdx.y * 64, blockN = blockIdx.x * 64;

    int rowA = t >> 2, kA = (t & 3) * 4;     // A tile: 64 rows x 16 k
    int rowB = t >> 4, colB = (t & 15) * 4;  // B tile: 16 k x 64 cols
    bool aValid = (blockM + rowA) < M;

    float acc[4][4] = {};
    for (int k0 = 0; k0 < K; k0 += 16) {
        float4 av = aValid
            ? *(const float4*)(A + (size_t)(blockM + rowA) * K + k0 + kA)
            : make_float4(0.f, 0.f, 0.f, 0.f);
        float4 bv = *(const float4*)(B + (size_t)(k0 + rowB) * N + blockN + colB);
        As[kA + 0][rowA] = av.x; As[kA + 1][rowA] = av.y;
        As[kA + 2][rowA] = av.z; As[kA + 3][rowA] = av.w;
        *(float4*)&Bs[rowB][colB] = bv;
        __syncthreads();
        #pragma unroll
        for (int k = 0; k < 16; k++) {
            float a[4], b[4];
            #pragma unroll
            for (int i = 0; i < 4; i++) a[i] = As[k][ty * 4 + i];
            #pragma unroll
            for (int j = 0; j < 4; j++) b[j] = Bs[k][tx * 4 + j];
            #pragma unroll
            for (int i = 0; i < 4; i++)
                #pragma unroll
                for (int j = 0; j < 4; j++)
                    acc[i][j] += a[i] * b[j];
        }
        __syncthreads();
    }
    #pragma unroll
    for (int i = 0; i < 4; i++) {
        int row = blockM + ty * 4 + i;
        if (row < M) {
            float* cp = C + (size_t)row * ldc + coff + blockN + tx * 4;
            #pragma unroll
            for (int j = 0; j < 4; j++) cp[j] = acc[i][j];
        }
    }
}

// ---------------- attention dot products (warp per node) --------------------
// h: [N, 2*C]; attS/attD: [2, C]; outputs asrc/adst: [N, 2]
template <int C>
__global__ void attn_dots_kernel(const float* __restrict__ h,
                                 const float* __restrict__ attS,
                                 const float* __restrict__ attD,
                                 float* __restrict__ asrc, float* __restrict__ adst,
                                 int n_nodes) {
    int w = (blockIdx.x * blockDim.x + threadIdx.x) >> 5;
    int lane = threadIdx.x & 31;
    if (w >= n_nodes) return;
    const float* hp = h + (size_t)w * 2 * C;
    float s0 = 0.f, d0 = 0.f, s1 = 0.f, d1 = 0.f;
    for (int c = lane; c < C; c += 32) {
        float h0 = hp[c], h1 = hp[C + c];
        s0 += h0 * attS[c];       d0 += h0 * attD[c];
        s1 += h1 * attS[C + c];   d1 += h1 * attD[C + c];
    }
    #pragma unroll
    for (int o = 16; o; o >>= 1) {
        s0 += __shfl_xor_sync(0xffffffffu, s0, o);
        d0 += __shfl_xor_sync(0xffffffffu, d0, o);
        s1 += __shfl_xor_sync(0xffffffffu, s1, o);
        d1 += __shfl_xor_sync(0xffffffffu, d1, o);
    }
    if (lane == 0) {
        asrc[2 * w] = s0; asrc[2 * w + 1] = s1;
        adst[2 * w] = d0; adst[2 * w + 1] = d1;
    }
}

__device__ __forceinline__ float lrelu(float x) { return x > 0.f ? x : 0.2f * x; }

// ---------------- GAT aggregation: warp per destination node ----------------
// 2 independent heads, C channels each; CSR over incoming edges.
template <int C, bool ELU>
__global__ void gat_aggregate_kernel(const float* __restrict__ asrc,
                                     const float* __restrict__ adst,
                                     const float* __restrict__ h,     // [N, 2*C]
                                     const float* __restrict__ bias0,
                                     const float* __restrict__ bias1,
                                     float* __restrict__ out0, int stride0,
                                     float* __restrict__ out1, int stride1,
                                     int n_nodes) {
    int w = (blockIdx.x * blockDim.x + threadIdx.x) >> 5;
    int lane = threadIdx.x & 31;
    if (w >= n_nodes) return;
    int s0 = g_off[w], s1 = g_off[w + 1];
    float ad0 = adst[2 * w], ad1 = adst[2 * w + 1];

    // pass 1: per-head max
    float m0 = -1e30f, m1 = -1e30f;
    for (int i = s0 + lane; i < s1; i += 32) {
        int s = g_srcList[i];
        float e0 = lrelu(asrc[2 * s] + ad0);
        float e1 = lrelu(asrc[2 * s + 1] + ad1);
        m0 = fmaxf(m0, e0); m1 = fmaxf(m1, e1);
    }
    #pragma unroll
    for (int o = 16; o; o >>= 1) {
        m0 = fmaxf(m0, __shfl_xor_sync(0xffffffffu, m0, o));
        m1 = fmaxf(m1, __shfl_xor_sync(0xffffffffu, m1, o));
    }
    // pass 2: denominators
    float den0 = 0.f, den1 = 0.f;
    for (int i = s0 + lane; i < s1; i += 32) {
        int s = g_srcList[i];
        float e0 = lrelu(asrc[2 * s] + ad0);
        float e1 = lrelu(asrc[2 * s + 1] + ad1);
        den0 += __expf(e0 - m0); den1 += __expf(e1 - m1);
    }
    #pragma unroll
    for (int o = 16; o; o >>= 1) {
        den0 += __shfl_xor_sync(0xffffffffu, den0, o);
        den1 += __shfl_xor_sync(0xffffffffu, den1, o);
    }
    float inv0 = 1.f / (den0 + 1e-16f);
    float inv1 = 1.f / (den1 + 1e-16f);

    // pass 3: weighted feature accumulation (whole warp walks each edge)
    constexpr int V = C / 32;  // 4 (layer1) or 2 (layer2)
    float acc0[V], acc1[V];
    #pragma unroll
    for (int v = 0; v < V; v++) { acc0[v] = 0.f; acc1[v] = 0.f; }
    for (int i = s0; i < s1; i++) {
        int s = g_srcList[i];
        float w0 = __expf(lrelu(asrc[2 * s] + ad0) - m0) * inv0;
        float w1 = __expf(lrelu(asrc[2 * s + 1] + ad1) - m1) * inv1;
        const float* hp = h + (size_t)s * (2 * C);
        if constexpr (V == 4) {
            float4 v0 = *(const float4*)(hp + lane * 4);
            float4 v1 = *(const float4*)(hp + C + lane * 4);
            acc0[0] += w0 * v0.x; acc0[1] += w0 * v0.y;
            acc0[2] += w0 * v0.z; acc0[3] += w0 * v0.w;
            acc1[0] += w1 * v1.x; acc1[1] += w1 * v1.y;
            acc1[2] += w1 * v1.z; acc1[3] += w1 * v1.w;
        } else {
            float2 v0 = *(const float2*)(hp + lane * 2);
            float2 v1 = *(const float2*)(hp + C + lane * 2);
            acc0[0] += w0 * v0.x; acc0[1] += w0 * v0.y;
            acc1[0] += w1 * v1.x; acc1[1] += w1 * v1.y;
        }
    }
    float* o0 = out0 + (size_t)w * stride0 + lane * V;
    float* o1 = out1 + (size_t)w * stride1 + lane * V;
    #pragma unroll
    for (int v = 0; v < V; v++) {
        float r0 = acc0[v] + bias0[lane * V + v];
        float r1 = acc1[v] + bias1[lane * V + v];
        if constexpr (ELU) {
            r0 = r0 > 0.f ? r0 : expm1f(r0);
            r1 = r1 > 0.f ? r1 : expm1f(r1);
        }
        o0[v] = r0; o1[v] = r1;
    }
}

// ---------------- host launch ------------------------------------------------
static void* sym(const void* s) { void* p = nullptr; cudaGetSymbolAddress(&p, s); return p; }

extern "C" void kernel_launch(void* const* d_in, const int* in_sizes, int n_in,
                              void* d_out, int out_size) {
    const float* x        = (const float*)d_in[0];
    const int*   ei       = (const int*)d_in[1];
    const float* W1       = (const float*)d_in[2];
    const float* attS1    = (const float*)d_in[3];
    const float* attD1    = (const float*)d_in[4];
    const float* b1       = (const float*)d_in[5];
    const float* Wmu      = (const float*)d_in[6];
    const float* attSmu   = (const float*)d_in[7];
    const float* attDmu   = (const float*)d_in[8];
    const float* bmu      = (const float*)d_in[9];
    const float* Wls      = (const float*)d_in[10];
    const float* attSls   = (const float*)d_in[11];
    const float* attDls   = (const float*)d_in[12];
    const float* bls      = (const float*)d_in[13];
    float* out = (float*)d_out;

    float* H1 = (float*)sym(g_H1);
    float* O1 = (float*)sym(g_O1);
    float* H2 = (float*)sym(g_H2);
    float* as1 = (float*)sym(g_as1); float* ad1 = (float*)sym(g_ad1);
    float* as2 = (float*)sym(g_as2); float* ad2 = (float*)sym(g_ad2);
    int* deg = (int*)sym(g_deg);
    int* off = (int*)sym(g_off);
    int* cur = (int*)sym(g_cur);
    int* srcL = (int*)sym(g_srcList);
    float* S2 = (float*)sym(g_attS2); float* D2 = (float*)sym(g_attD2);

    const int N = NNODES;
    const int warpBlocks = (N * 32 + 255) / 256;

    // CSR build
    zero_int_kernel<<<(N + 1 + 255) / 256, 256>>>(deg, N + 1);
    hist_kernel<<<(E_TOT + 255) / 256, 256>>>(ei, deg);
    scan_kernel<<<1, 1024>>>(deg, off, N, E_TOT);
    copy_int_kernel<<<(N + 255) / 256, 256>>>(off, cur, N);
    scatter_kernel<<<(E_TOT + 255) / 256, 256>>>(ei, cur, srcL);

    // layer 1: H1 = x @ W1 ; attention dots ; aggregate (+bias, ELU)
    {
        dim3 grid(256 / 64, (N + 63) / 64);
        gemm_kernel<<<grid, 256>>>(x, W1, H1, N, INCH, 256, 256, 0);
    }
    attn_dots_kernel<128><<<warpBlocks, 256>>>(H1, attS1, attD1, as1, ad1, N);
    gat_aggregate_kernel<128, true><<<warpBlocks, 256>>>(
        as1, ad1, H1, b1, b1 + 128, O1, 256, O1 + 128, 256, N);

    // layer 2: H2 = [O1 @ Wmu | O1 @ Wls]; dots; aggregate -> d_out
    {
        dim3 grid(1, (N + 63) / 64);
        gemm_kernel<<<grid, 256>>>(O1, Wmu, H2, N, 256, 64, 128, 0);
        gemm_kernel<<<grid, 256>>>(O1, Wls, H2, N, 256, 64, 128, 64);
    }
    pack_att_kernel<<<1, 64>>>(attSmu, attSls, attDmu, attDls, S2, D2);
    attn_dots_kernel<64><<<warpBlocks, 256>>>(H2, S2, D2, as2, ad2, N);
    gat_aggregate_kernel<64, false><<<warpBlocks, 256>>>(
        as2, ad2, H2, bmu, bls,
        out, 64, out + (size_t)N * 64, 64, N);
}

// round 5
// speedup vs baseline: 1.1946x; 1.1946x over previous
#include <cuda_runtime.h>
#include <cuda_bf16.h>
#include <stdint.h>
#include <math.h>

#define NNODES 50000
#define INCH   128
#define E_REAL 400000
#define E_TOT  450000

typedef unsigned int u32;

// ---------------- scratch (device globals) ----------------------------------
__device__ __align__(16) float g_H1[(size_t)NNODES * 256];
__device__ __align__(16) float g_H2[(size_t)NNODES * 128];
__device__ __align__(16) __nv_bfloat16 g_xhi[(size_t)NNODES * 128];
__device__ __align__(16) __nv_bfloat16 g_xlo[(size_t)NNODES * 128];
__device__ __align__(16) __nv_bfloat16 g_O1hi[(size_t)NNODES * 256];
__device__ __align__(16) __nv_bfloat16 g_O1lo[(size_t)NNODES * 256];
__device__ __align__(16) __nv_bfloat16 g_B1thi[256 * 128];
__device__ __align__(16) __nv_bfloat16 g_B1tlo[256 * 128];
__device__ __align__(16) __nv_bfloat16 g_B2thi[128 * 256];
__device__ __align__(16) __nv_bfloat16 g_B2tlo[128 * 256];
__device__ float g_as1[NNODES * 2];
__device__ float g_ad1[NNODES * 2];
__device__ float g_as2[NNODES * 2];
__device__ float g_ad2[NNODES * 2];
__device__ int   g_deg[NNODES + 1];
__device__ int   g_off[NNODES + 1];
__device__ int   g_cur[NNODES];
__device__ int   g_srcList[E_TOT];
__device__ float g_attS2[128];
__device__ float g_attD2[128];

// ---------------- small utility kernels -------------------------------------
__global__ void zero_int_kernel(int* p, int n)
{
    int i = blockIdx.x * blockDim.x + threadIdx.x;
    if (i < n) { p[i] = 0; }
}

__global__ void copy_int_kernel(const int* __restrict__ a, int* __restrict__ b, int n)
{
    int i = blockIdx.x * blockDim.x + threadIdx.x;
    if (i < n) { b[i] = a[i]; }
}

__global__ void hist_kernel(const int* __restrict__ ei, int* __restrict__ deg)
{
    int i = blockIdx.x * blockDim.x + threadIdx.x;
    if (i >= E_TOT) { return; }
    int dst = (i < E_REAL) ? ei[E_REAL + i] : (i - E_REAL);
    atomicAdd(&deg[dst], 1);
}

__global__ void scan_kernel(const int* __restrict__ deg, int* __restrict__ off,
                            int n, int total)
{
    __shared__ int warpSums[32];
    __shared__ int s_carry;
    int tid = threadIdx.x;
    int lane = tid & 31;
    int wid = tid >> 5;
    if (tid == 0) { s_carry = 0; }
    __syncthreads();
    for (int base = 0; base < n; base += 1024) {
        int idx = base + tid;
        int v = (idx < n) ? deg[idx] : 0;
        int x = v;
        for (int o = 1; o < 32; o <<= 1) {
            int y = __shfl_up_sync(0xffffffffu, x, o);
            if (lane >= o) { x += y; }
        }
        if (lane == 31) { warpSums[wid] = x; }
        __syncthreads();
        if (wid == 0) {
            int w = warpSums[lane];
            for (int o = 1; o < 32; o <<= 1) {
                int y = __shfl_up_sync(0xffffffffu, w, o);
                if (lane >= o) { w += y; }
            }
            warpSums[lane] = w;
        }
        __syncthreads();
        int blockIncl = x + ((wid > 0) ? warpSums[wid - 1] : 0);
        int excl = blockIncl - v;
        if (idx < n) { off[idx] = s_carry + excl; }
        __syncthreads();
        if (tid == 1023) { s_carry += blockIncl; }
        __syncthreads();
    }
    if (tid == 0) { off[n] = total; }
}

__global__ void scatter_kernel(const int* __restrict__ ei, int* __restrict__ cur,
                               int* __restrict__ srcList)
{
    int i = blockIdx.x * blockDim.x + threadIdx.x;
    if (i >= E_TOT) { return; }
    int src;
    int dst;
    if (i < E_REAL) { src = ei[i]; dst = ei[E_REAL + i]; }
    else            { src = i - E_REAL; dst = src; }
    int p = atomicAdd(&cur[dst], 1);
    srcList[p] = src;
}

__global__ void pack_att_kernel(const float* smu, const float* sls,
                                const float* dmu, const float* dls,
                                float* S, float* D)
{
    int i = threadIdx.x;  // 64 threads
    S[i] = smu[i];
    S[64 + i] = sls[i];
    D[i] = dmu[i];
    D[64 + i] = dls[i];
}

__global__ void split_kernel(const float* __restrict__ x,
                             __nv_bfloat16* __restrict__ hi,
                             __nv_bfloat16* __restrict__ lo, int n)
{
    int i = blockIdx.x * blockDim.x + threadIdx.x;
    if (i >= n) { return; }
    float v = x[i];
    __nv_bfloat16 h = __float2bfloat16(v);
    hi[i] = h;
    lo[i] = __float2bfloat16(v - __bfloat162float(h));
}

__global__ void packW1_kernel(const float* __restrict__ W1,
                              __nv_bfloat16* __restrict__ hi,
                              __nv_bfloat16* __restrict__ lo)
{
    int i = blockIdx.x * blockDim.x + threadIdx.x;
    if (i >= 256 * 128) { return; }
    int nn = i >> 7;
    int kk = i & 127;
    float v = W1[kk * 256 + nn];
    __nv_bfloat16 h = __float2bfloat16(v);
    hi[i] = h;
    lo[i] = __float2bfloat16(v - __bfloat162float(h));
}

__global__ void packW2_kernel(const float* __restrict__ Wmu,
                              const float* __restrict__ Wls,
                              __nv_bfloat16* __restrict__ hi,
                              __nv_bfloat16* __restrict__ lo)
{
    int i = blockIdx.x * blockDim.x + threadIdx.x;
    if (i >= 128 * 256) { return; }
    int nn = i >> 8;
    int kk = i & 255;
    float v = (nn < 64) ? Wmu[kk * 64 + nn] : Wls[kk * 64 + (nn - 64)];
    __nv_bfloat16 h = __float2bfloat16(v);
    hi[i] = h;
    lo[i] = __float2bfloat16(v - __bfloat162float(h));
}

// ---------------- bf16x3 tensor-core GEMM ------------------------------------
__device__ __forceinline__ void ldsm4(u32* r, const void* p)
{
    u32 addr = (u32)__cvta_generic_to_shared(p);
    asm volatile("ldmatrix.sync.aligned.m8n8.x4.shared.b16 {%0,%1,%2,%3}, [%4];"
        : "=r"(r[0]), "=r"(r[1]), "=r"(r[2]), "=r"(r[3]) : "r"(addr));
}

__device__ __forceinline__ void mma16816(float* c, const u32* a, const u32* b)
{
    asm volatile("mma.sync.aligned.m16n8k16.row.col.f32.bf16.bf16.f32 "
        "{%0,%1,%2,%3}, {%4,%5,%6,%7}, {%8,%9}, {%0,%1,%2,%3};"
        : "+f"(c[0]), "+f"(c[1]), "+f"(c[2]), "+f"(c[3])
        : "r"(a[0]), "r"(a[1]), "r"(a[2]), "r"(a[3]), "r"(b[0]), "r"(b[1]));
}

// C[M,N] = (Ahi+Alo)[M,K] @ (Bthi+Btlo)[N,K]^T.  N % 128 == 0, K % 32 == 0.
__global__ __launch_bounds__(256, 1)
void gemm_bf16x3_kernel(const __nv_bfloat16* __restrict__ Ahi,
                        const __nv_bfloat16* __restrict__ Alo,
                        const __nv_bfloat16* __restrict__ Bthi,
                        const __nv_bfloat16* __restrict__ Btlo,
                        float* __restrict__ C, int M, int K, int N)
{
    __shared__ __nv_bfloat16 sAhi[128][40];
    __shared__ __nv_bfloat16 sAlo[128][40];
    __shared__ __nv_bfloat16 sBhi[128][40];
    __shared__ __nv_bfloat16 sBlo[128][40];

    int tid = threadIdx.x;
    int warp = tid >> 5;
    int lane = tid & 31;
    int wm = warp >> 2;
    int wn = warp & 3;
    int m0 = blockIdx.y * 128;
    int n0 = blockIdx.x * 128;

    float acc[4][4][4];
    for (int a = 0; a < 4; a++) {
        for (int b = 0; b < 4; b++) {
            for (int c = 0; c < 4; c++) { acc[a][b][c] = 0.0f; }
        }
    }

    for (int k0 = 0; k0 < K; k0 += 32) {
        for (int i = 0; i < 4; i++) {
            int c = tid + 256 * i;
            int r = c >> 3;
            int kk = (c & 7) * 4;
            int grow = m0 + r;
            uint2 vh;
            uint2 vl;
            vh.x = 0u; vh.y = 0u;
            vl.x = 0u; vl.y = 0u;
            if (grow < M) {
                vh = *(const uint2*)(Ahi + (size_t)grow * K + k0 + kk);
                vl = *(const uint2*)(Alo + (size_t)grow * K + k0 + kk);
            }
            *(uint2*)&sAhi[r][kk] = vh;
            *(uint2*)&sAlo[r][kk] = vl;
            int gn = n0 + r;
            *(uint2*)&sBhi[r][kk] = *(const uint2*)(Bthi + (size_t)gn * K + k0 + kk);
            *(uint2*)&sBlo[r][kk] = *(const uint2*)(Btlo + (size_t)gn * K + k0 + kk);
        }
        __syncthreads();

        for (int ks = 0; ks < 2; ks++) {
            int colOff = ks * 16 + ((lane >> 4) << 3);
            int rsel = lane & 15;
            u32 Ah[4][4];
            u32 Al[4][4];
            u32 Bh[4][2];
            u32 Bl[4][2];
            for (int mf = 0; mf < 4; mf++) {
                ldsm4(Ah[mf], &sAhi[wm * 64 + mf * 16 + rsel][colOff]);
                ldsm4(Al[mf], &sAlo[wm * 64 + mf * 16 + rsel][colOff]);
            }
            for (int p = 0; p < 2; p++) {
                u32 t[4];
                ldsm4(t, &sBhi[wn * 32 + p * 16 + rsel][colOff]);
                Bh[2 * p][0] = t[0];
                Bh[2 * p][1] = t[2];
                Bh[2 * p + 1][0] = t[1];
                Bh[2 * p + 1][1] = t[3];
                ldsm4(t, &sBlo[wn * 32 + p * 16 + rsel][colOff]);
                Bl[2 * p][0] = t[0];
                Bl[2 * p][1] = t[2];
                Bl[2 * p + 1][0] = t[1];
                Bl[2 * p + 1][1] = t[3];
            }
            for (int mf = 0; mf < 4; mf++) {
                for (int nf = 0; nf < 4; nf++) {
                    mma16816(acc[mf][nf], Ah[mf], Bh[nf]);
                    mma16816(acc[mf][nf], Ah[mf], Bl[nf]);
                    mma16816(acc[mf][nf], Al[mf], Bh[nf]);
                }
            }
        }
        __syncthreads();
    }

    for (int mf = 0; mf < 4; mf++) {
        int r0 = m0 + wm * 64 + mf * 16 + (lane >> 2);
        for (int nf = 0; nf < 4; nf++) {
            int cb = n0 + wn * 32 + nf * 8 + (lane & 3) * 2;
            if (r0 < M) {
                float2 v;
                v.x = acc[mf][nf][0];
                v.y = acc[mf][nf][1];
                *(float2*)&C[(size_t)r0 * N + cb] = v;
            }
            if (r0 + 8 < M) {
                float2 v;
                v.x = acc[mf][nf][2];
                v.y = acc[mf][nf][3];
                *(float2*)&C[(size_t)(r0 + 8) * N + cb] = v;
            }
        }
    }
}

// ---------------- attention dot products (warp per node) ---------------------
template <int C>
__global__ void attn_dots_kernel(const float* __restrict__ h,
                                 const float* __restrict__ attS,
                                 const float* __restrict__ attD,
                                 float* __restrict__ asrc,
                                 float* __restrict__ adst,
                                 int n_nodes)
{
    int w = (blockIdx.x * blockDim.x + threadIdx.x) >> 5;
    int lane = threadIdx.x & 31;
    if (w >= n_nodes) { return; }
    const float* hp = h + (size_t)w * 2 * C;
    float s0 = 0.0f;
    float d0 = 0.0f;
    float s1 = 0.0f;
    float d1 = 0.0f;
    for (int c = lane; c < C; c += 32) {
        float h0 = hp[c];
        float h1 = hp[C + c];
        s0 += h0 * attS[c];
        d0 += h0 * attD[c];
        s1 += h1 * attS[C + c];
        d1 += h1 * attD[C + c];
    }
    for (int o = 16; o > 0; o >>= 1) {
        s0 += __shfl_xor_sync(0xffffffffu, s0, o);
        d0 += __shfl_xor_sync(0xffffffffu, d0, o);
        s1 += __shfl_xor_sync(0xffffffffu, s1, o);
        d1 += __shfl_xor_sync(0xffffffffu, d1, o);
    }
    if (lane == 0) {
        asrc[2 * w] = s0;
        asrc[2 * w + 1] = s1;
        adst[2 * w] = d0;
        adst[2 * w + 1] = d1;
    }
}

__device__ __forceinline__ float lrelu(float x)
{
    return (x > 0.0f) ? x : 0.2f * x;
}

// ---------------- layer-1 aggregation (ELU + bf16 split out) -----------------
__global__ void gat_agg_l1_kernel(const float* __restrict__ asrc,
                                  const float* __restrict__ adst,
                                  const float* __restrict__ h,
                                  const float* __restrict__ bias,
                                  __nv_bfloat16* __restrict__ ohi,
                                  __nv_bfloat16* __restrict__ olo,
                                  int n_nodes)
{
    int w = (blockIdx.x * blockDim.x + threadIdx.x) >> 5;
    int lane = threadIdx.x & 31;
    if (w >= n_nodes) { return; }
    int s0 = g_off[w];
    int s1 = g_off[w + 1];
    float ad0 = adst[2 * w];
    float ad1 = adst[2 * w + 1];

    float m0 = -1e30f;
    float m1 = -1e30f;
    for (int i = s0 + lane; i < s1; i += 32) {
        int s = g_srcList[i];
        m0 = fmaxf(m0, lrelu(asrc[2 * s] + ad0));
        m1 = fmaxf(m1, lrelu(asrc[2 * s + 1] + ad1));
    }
    for (int o = 16; o > 0; o >>= 1) {
        m0 = fmaxf(m0, __shfl_xor_sync(0xffffffffu, m0, o));
        m1 = fmaxf(m1, __shfl_xor_sync(0xffffffffu, m1, o));
    }

    float den0 = 0.0f;
    float den1 = 0.0f;
    for (int i = s0 + lane; i < s1; i += 32) {
        int s = g_srcList[i];
        den0 += __expf(lrelu(asrc[2 * s] + ad0) - m0);
        den1 += __expf(lrelu(asrc[2 * s + 1] + ad1) - m1);
    }
    for (int o = 16; o > 0; o >>= 1) {
        den0 += __shfl_xor_sync(0xffffffffu, den0, o);
        den1 += __shfl_xor_sync(0xffffffffu, den1, o);
    }
    float inv0 = 1.0f / (den0 + 1e-16f);
    float inv1 = 1.0f / (den1 + 1e-16f);

    float acc0[4];
    float acc1[4];
    for (int v = 0; v < 4; v++) { acc0[v] = 0.0f; acc1[v] = 0.0f; }
    for (int i = s0; i < s1; i++) {
        int s = g_srcList[i];
        float w0 = __expf(lrelu(asrc[2 * s] + ad0) - m0) * inv0;
        float w1 = __expf(lrelu(asrc[2 * s + 1] + ad1) - m1) * inv1;
        const float* hp = h + (size_t)s * 256;
        float4 v0 = *(const float4*)(hp + lane * 4);
        float4 v1 = *(const float4*)(hp + 128 + lane * 4);
        acc0[0] += w0 * v0.x;
        acc0[1] += w0 * v0.y;
        acc0[2] += w0 * v0.z;
        acc0[3] += w0 * v0.w;
        acc1[0] += w1 * v1.x;
        acc1[1] += w1 * v1.y;
        acc1[2] += w1 * v1.z;
        acc1[3] += w1 * v1.w;
    }

    size_t base = (size_t)w * 256;
    for (int v = 0; v < 4; v++) {
        int c0 = lane * 4 + v;
        float r0 = acc0[v] + bias[c0];
        float r1 = acc1[v] + bias[128 + c0];
        r0 = (r0 > 0.0f) ? r0 : expm1f(r0);
        r1 = (r1 > 0.0f) ? r1 : expm1f(r1);
        __nv_bfloat16 h0 = __float2bfloat16(r0);
        __nv_bfloat16 h1 = __float2bfloat16(r1);
        ohi[base + c0] = h0;
        olo[base + c0] = __float2bfloat16(r0 - __bfloat162float(h0));
        ohi[base + 128 + c0] = h1;
        olo[base + 128 + c0] = __float2bfloat16(r1 - __bfloat162float(h1));
    }
}

// ---------------- layer-2 aggregation (mu | logstd, fp32 out) ----------------
__global__ void gat_agg_l2_kernel(const float* __restrict__ asrc,
                                  const float* __restrict__ adst,
                                  const float* __restrict__ h,
                                  const float* __restrict__ bmu,
                                  const float* __restrict__ bls,
                                  float* __restrict__ out_mu,
                                  float* __restrict__ out_ls,
                                  int n_nodes)
{
    int w = (blockIdx.x * blockDim.x + threadIdx.x) >> 5;
    int lane = threadIdx.x & 31;
    if (w >= n_nodes) { return; }
    int s0 = g_off[w];
    int s1 = g_off[w + 1];
    float ad0 = adst[2 * w];
    float ad1 = adst[2 * w + 1];

    float m0 = -1e30f;
    float m1 = -1e30f;
    for (int i = s0 + lane; i < s1; i += 32) {
        int s = g_srcList[i];
        m0 = fmaxf(m0, lrelu(asrc[2 * s] + ad0));
        m1 = fmaxf(m1, lrelu(asrc[2 * s + 1] + ad1));
    }
    for (int o = 16; o > 0; o >>= 1) {
        m0 = fmaxf(m0, __shfl_xor_sync(0xffffffffu, m0, o));
        m1 = fmaxf(m1, __shfl_xor_sync(0xffffffffu, m1, o));
    }

    float den0 = 0.0f;
    float den1 = 0.0f;
    for (int i = s0 + lane; i < s1; i += 32) {
        int s = g_srcList[i];
        den0 += __expf(lrelu(asrc[2 * s] + ad0) - m0);
        den1 += __expf(lrelu(asrc[2 * s + 1] + ad1) - m1);
    }
    for (int o = 16; o > 0; o >>= 1) {
        den0 += __shfl_xor_sync(0xffffffffu, den0, o);
        den1 += __shfl_xor_sync(0xffffffffu, den1, o);
    }
    float inv0 = 1.0f / (den0 + 1e-16f);
    float inv1 = 1.0f / (den1 + 1e-16f);

    float a00 = 0.0f;
    float a01 = 0.0f;
    float a10 = 0.0f;
    float a11 = 0.0f;
    for (int i = s0; i < s1; i++) {
        int s = g_srcList[i];
        float w0 = __expf(lrelu(asrc[2 * s] + ad0) - m0) * inv0;
        float w1 = __expf(lrelu(asrc[2 * s + 1] + ad1) - m1) * inv1;
        const float* hp = h + (size_t)s * 128;
        float2 v0 = *(const float2*)(hp + lane * 2);
        float2 v1 = *(const float2*)(hp + 64 + lane * 2);
        a00 += w0 * v0.x;
        a01 += w0 * v0.y;
        a10 += w1 * v1.x;
        a11 += w1 * v1.y;
    }
    float* o0 = out_mu + (size_t)w * 64 + lane * 2;
    float* o1 = out_ls + (size_t)w * 64 + lane * 2;
    o0[0] = a00 + bmu[lane * 2];
    o0[1] = a01 + bmu[lane * 2 + 1];
    o1[0] = a10 + bls[lane * 2];
    o1[1] = a11 + bls[lane * 2 + 1];
}

// ---------------- host launch ------------------------------------------------
static void* symaddr(const void* s)
{
    void* p = nullptr;
    cudaGetSymbolAddress(&p, s);
    return p;
}

extern "C" void kernel_launch(void* const* d_in, const int* in_sizes, int n_in,
                              void* d_out, int out_size)
{
    const float* x      = (const float*)d_in[0];
    const int*   ei     = (const int*)d_in[1];
    const float* W1     = (const float*)d_in[2];
    const float* attS1  = (const float*)d_in[3];
    const float* attD1  = (const float*)d_in[4];
    const float* b1     = (const float*)d_in[5];
    const float* Wmu    = (const float*)d_in[6];
    const float* attSmu = (const float*)d_in[7];
    const float* attDmu = (const float*)d_in[8];
    const float* bmu    = (const float*)d_in[9];
    const float* Wls    = (const float*)d_in[10];
    const float* attSls = (const float*)d_in[11];
    const float* attDls = (const float*)d_in[12];
    const float* bls    = (const float*)d_in[13];
    float* out = (float*)d_out;

    float* H1 = (float*)symaddr(g_H1);
    float* H2 = (float*)symaddr(g_H2);
    __nv_bfloat16* xhi   = (__nv_bfloat16*)symaddr(g_xhi);
    __nv_bfloat16* xlo   = (__nv_bfloat16*)symaddr(g_xlo);
    __nv_bfloat16* O1hi  = (__nv_bfloat16*)symaddr(g_O1hi);
    __nv_bfloat16* O1lo  = (__nv_bfloat16*)symaddr(g_O1lo);
    __nv_bfloat16* B1thi = (__nv_bfloat16*)symaddr(g_B1thi);
    __nv_bfloat16* B1tlo = (__nv_bfloat16*)symaddr(g_B1tlo);
    __nv_bfloat16* B2thi = (__nv_bfloat16*)symaddr(g_B2thi);
    __nv_bfloat16* B2tlo = (__nv_bfloat16*)symaddr(g_B2tlo);
    float* as1 = (float*)symaddr(g_as1);
    float* ad1 = (float*)symaddr(g_ad1);
    float* as2 = (float*)symaddr(g_as2);
    float* ad2 = (float*)symaddr(g_ad2);
    int* deg  = (int*)symaddr(g_deg);
    int* off  = (int*)symaddr(g_off);
    int* cur  = (int*)symaddr(g_cur);
    int* srcL = (int*)symaddr(g_srcList);
    float* S2 = (float*)symaddr(g_attS2);
    float* D2 = (float*)symaddr(g_attD2);

    const int N = NNODES;
    const int warpBlocks = (N * 32 + 255) / 256;

    // CSR build
    zero_int_kernel<<<(N + 1 + 255) / 256, 256>>>(deg, N + 1);
    hist_kernel<<<(E_TOT + 255) / 256, 256>>>(ei, deg);
    scan_kernel<<<1, 1024>>>(deg, off, N, E_TOT);
    copy_int_kernel<<<(N + 255) / 256, 256>>>(off, cur, N);
    scatter_kernel<<<(E_TOT + 255) / 256, 256>>>(ei, cur, srcL);

    // bf16 splits / weight packing
    split_kernel<<<(N * INCH + 255) / 256, 256>>>(x, xhi, xlo, N * INCH);
    packW1_kernel<<<(256 * 128 + 255) / 256, 256>>>(W1, B1thi, B1tlo);
    packW2_kernel<<<(128 * 256 + 255) / 256, 256>>>(Wmu, Wls, B2thi, B2tlo);

    // layer 1
    dim3 grid1(2, (N + 127) / 128);
    gemm_bf16x3_kernel<<<grid1, 256>>>(xhi, xlo, B1thi, B1tlo, H1, N, 128, 256);
    attn_dots_kernel<128><<<warpBlocks, 256>>>(H1, attS1, attD1, as1, ad1, N);
    gat_agg_l1_kernel<<<warpBlocks, 256>>>(as1, ad1, H1, b1, O1hi, O1lo, N);

    // layer 2
    dim3 grid2(1, (N + 127) / 128);
    gemm_bf16x3_kernel<<<grid2, 256>>>(O1hi, O1lo, B2thi, B2tlo, H2, N, 256, 128);
    pack_att_kernel<<<1, 64>>>(attSmu, attSls, attDmu, attDls, S2, D2);
    attn_dots_kernel<64><<<warpBlocks, 256>>>(H2, S2, D2, as2, ad2, N);
    gat_agg_l2_kernel<<<warpBlocks, 256>>>(as2, ad2, H2, bmu, bls,
                                           out, out + (size_t)N * 64, N);
}

// round 7
// speedup vs baseline: 1.2023x; 1.0064x over previous
#include <cuda_runtime.h>
#include <cuda_bf16.h>
#include <stdint.h>
#include <math.h>

#define NNODES 50000
#define INCH   128
#define E_REAL 400000
#define E_TOT  450000

typedef unsigned int u32;

// ---------------- scratch (device globals) ----------------------------------
__device__ __align__(16) float g_H1[(size_t)NNODES * 256];
__device__ __align__(16) float g_H2[(size_t)NNODES * 128];
__device__ __align__(16) __nv_bfloat16 g_O1hi[(size_t)NNODES * 256];
__device__ __align__(16) __nv_bfloat16 g_O1lo[(size_t)NNODES * 256];
__device__ __align__(16) __nv_bfloat16 g_B1thi[256 * 128];
__device__ __align__(16) __nv_bfloat16 g_B1tlo[256 * 128];
__device__ __align__(16) __nv_bfloat16 g_B2thi[128 * 256];
__device__ __align__(16) __nv_bfloat16 g_B2tlo[128 * 256];
__device__ __align__(16) float g_WA1[128 * 4];
__device__ float g_as1[NNODES * 2];
__device__ float g_ad1[NNODES * 2];
__device__ float g_as2[NNODES * 2];
__device__ float g_ad2[NNODES * 2];
__device__ int   g_deg[NNODES + 1];
__device__ int   g_off[NNODES + 1];
__device__ int   g_cur[NNODES];
__device__ int   g_srcList[E_TOT];
__device__ float g_attS2[128];
__device__ float g_attD2[128];

// ---------------- small utility kernels -------------------------------------
__global__ void zero_int_kernel(int* p, int n)
{
    int i = blockIdx.x * blockDim.x + threadIdx.x;
    if (i < n) { p[i] = 0; }
}

__global__ void hist_kernel(const int* __restrict__ ei, int* __restrict__ deg)
{
    int i = blockIdx.x * blockDim.x + threadIdx.x;
    if (i >= E_TOT) { return; }
    int dst = (i < E_REAL) ? ei[E_REAL + i] : (i - E_REAL);
    atomicAdd(&deg[dst], 1);
}

// exclusive scan; also initializes cur = off
__global__ void scan_kernel(const int* __restrict__ deg, int* __restrict__ off,
                            int* __restrict__ cur, int n, int total)
{
    __shared__ int warpSums[32];
    __shared__ int s_carry;
    int tid = threadIdx.x;
    int lane = tid & 31;
    int wid = tid >> 5;
    if (tid == 0) { s_carry = 0; }
    __syncthreads();
    for (int base = 0; base < n; base += 1024) {
        int idx = base + tid;
        int v = (idx < n) ? deg[idx] : 0;
        int x = v;
        for (int o = 1; o < 32; o <<= 1) {
            int y = __shfl_up_sync(0xffffffffu, x, o);
            if (lane >= o) { x += y; }
        }
        if (lane == 31) { warpSums[wid] = x; }
        __syncthreads();
        if (wid == 0) {
            int w = warpSums[lane];
            for (int o = 1; o < 32; o <<= 1) {
                int y = __shfl_up_sync(0xffffffffu, w, o);
                if (lane >= o) { w += y; }
            }
            warpSums[lane] = w;
        }
        __syncthreads();
        int blockIncl = x + ((wid > 0) ? warpSums[wid - 1] : 0);
        int excl = blockIncl - v;
        if (idx < n) {
            int val = s_carry + excl;
            off[idx] = val;
            cur[idx] = val;
        }
        __syncthreads();
        if (tid == 1023) { s_carry += blockIncl; }
        __syncthreads();
    }
    if (tid == 0) { off[n] = total; }
}

__global__ void scatter_kernel(const int* __restrict__ ei, int* __restrict__ cur,
                               int* __restrict__ srcList)
{
    int i = blockIdx.x * blockDim.x + threadIdx.x;
    if (i >= E_TOT) { return; }
    int src;
    int dst;
    if (i < E_REAL) { src = ei[i]; dst = ei[E_REAL + i]; }
    else            { src = i - E_REAL; dst = src; }
    int p = atomicAdd(&cur[dst], 1);
    srcList[p] = src;
}

__global__ void pack_att_kernel(const float* smu, const float* sls,
                                const float* dmu, const float* dls,
                                float* S, float* D)
{
    int i = threadIdx.x;  // 64 threads
    S[i] = smu[i];
    S[64 + i] = sls[i];
    D[i] = dmu[i];
    D[64 + i] = dls[i];
}

// WA1[k][j]: j=0 src h0, j=1 src h1, j=2 dst h0, j=3 dst h1
__global__ void fold_att1_kernel(const float* __restrict__ W1,
                                 const float* __restrict__ attS,
                                 const float* __restrict__ attD,
                                 float* __restrict__ WA)
{
    int t = threadIdx.x;  // 512 threads
    int k = t >> 2;
    int j = t & 3;
    int h = j & 1;
    const float* av = (j < 2) ? attS : attD;
    float s = 0.0f;
    for (int c = 0; c < 128; c++) {
        s += W1[k * 256 + h * 128 + c] * av[h * 128 + c];
    }
    WA[k * 4 + j] = s;
}

__global__ void packW1_kernel(const float* __restrict__ W1,
                              __nv_bfloat16* __restrict__ hi,
                              __nv_bfloat16* __restrict__ lo)
{
    int i = blockIdx.x * blockDim.x + threadIdx.x;
    if (i >= 256 * 128) { return; }
    int nn = i >> 7;
    int kk = i & 127;
    float v = W1[kk * 256 + nn];
    __nv_bfloat16 h = __float2bfloat16(v);
    hi[i] = h;
    lo[i] = __float2bfloat16(v - __bfloat162float(h));
}

__global__ void packW2_kernel(const float* __restrict__ Wmu,
                              const float* __restrict__ Wls,
                              __nv_bfloat16* __restrict__ hi,
                              __nv_bfloat16* __restrict__ lo)
{
    int i = blockIdx.x * blockDim.x + threadIdx.x;
    if (i >= 128 * 256) { return; }
    int nn = i >> 8;
    int kk = i & 255;
    float v = (nn < 64) ? Wmu[kk * 64 + nn] : Wls[kk * 64 + (nn - 64)];
    __nv_bfloat16 h = __float2bfloat16(v);
    hi[i] = h;
    lo[i] = __float2bfloat16(v - __bfloat162float(h));
}

// ---------------- bf16x3 tensor-core GEMM ------------------------------------
__device__ __forceinline__ void ldsm4(u32* r, const void* p)
{
    u32 addr = (u32)__cvta_generic_to_shared(p);
    asm volatile("ldmatrix.sync.aligned.m8n8.x4.shared.b16 {%0,%1,%2,%3}, [%4];"
        : "=r"(r[0]), "=r"(r[1]), "=r"(r[2]), "=r"(r[3]) : "r"(addr));
}

__device__ __forceinline__ void mma16816(float* c, const u32* a, const u32* b)
{
    asm volatile("mma.sync.aligned.m16n8k16.row.col.f32.bf16.bf16.f32 "
        "{%0,%1,%2,%3}, {%4,%5,%6,%7}, {%8,%9}, {%0,%1,%2,%3};"
        : "+f"(c[0]), "+f"(c[1]), "+f"(c[2]), "+f"(c[3])
        : "r"(a[0]), "r"(a[1]), "r"(a[2]), "r"(a[3]), "r"(b[0]), "r"(b[1]));
}

// C[M,N] = A[M,K] @ Bt[N,K]^T with bf16x3.
// SPLITA==false: A given as fp32 (Af), converted to hi/lo in the loader.
// SPLITA==true:  A given as bf16 hi/lo pair.
template <bool SPLITA>
__global__ __launch_bounds__(256, 1)
void gemm_bf16x3_kernel(const float* __restrict__ Af,
                        const __nv_bfloat16* __restrict__ Ahi,
                        const __nv_bfloat16* __restrict__ Alo,
                        const __nv_bfloat16* __restrict__ Bthi,
                        const __nv_bfloat16* __restrict__ Btlo,
                        float* __restrict__ C, int M, int K, int N)
{
    __shared__ __nv_bfloat16 sAhi[128][40];
    __shared__ __nv_bfloat16 sAlo[128][40];
    __shared__ __nv_bfloat16 sBhi[128][40];
    __shared__ __nv_bfloat16 sBlo[128][40];

    int tid = threadIdx.x;
    int warp = tid >> 5;
    int lane = tid & 31;
    int wm = warp >> 2;
    int wn = warp & 3;
    int m0 = blockIdx.y * 128;
    int n0 = blockIdx.x * 128;

    float acc[4][4][4];
    for (int a = 0; a < 4; a++) {
        for (int b = 0; b < 4; b++) {
            for (int c = 0; c < 4; c++) { acc[a][b][c] = 0.0f; }
        }
    }

    for (int k0 = 0; k0 < K; k0 += 32) {
        for (int i = 0; i < 4; i++) {
            int c = tid + 256 * i;
            int r = c >> 3;
            int kk = (c & 7) * 4;
            int grow = m0 + r;
            if (SPLITA) {
                uint2 vh;
                uint2 vl;
                vh.x = 0u; vh.y = 0u;
                vl.x = 0u; vl.y = 0u;
                if (grow < M) {
                    vh = *(const uint2*)(Ahi + (size_t)grow * K + k0 + kk);
                    vl = *(const uint2*)(Alo + (size_t)grow * K + k0 + kk);
                }
                *(uint2*)&sAhi[r][kk] = vh;
                *(uint2*)&sAlo[r][kk] = vl;
            } else {
                float4 v;
                v.x = 0.0f; v.y = 0.0f; v.z = 0.0f; v.w = 0.0f;
                if (grow < M) {
                    v = *(const float4*)(Af + (size_t)grow * K + k0 + kk);
                }
                __nv_bfloat16 h0 = __float2bfloat16(v.x);
                __nv_bfloat16 h1 = __float2bfloat16(v.y);
                __nv_bfloat16 h2 = __float2bfloat16(v.z);
                __nv_bfloat16 h3 = __float2bfloat16(v.w);
                __nv_bfloat16 l0 = __float2bfloat16(v.x - __bfloat162float(h0));
                __nv_bfloat16 l1 = __float2bfloat16(v.y - __bfloat162float(h1));
                __nv_bfloat16 l2 = __float2bfloat16(v.z - __bfloat162float(h2));
                __nv_bfloat16 l3 = __float2bfloat16(v.w - __bfloat162float(h3));
                sAhi[r][kk + 0] = h0;
                sAhi[r][kk + 1] = h1;
                sAhi[r][kk + 2] = h2;
                sAhi[r][kk + 3] = h3;
                sAlo[r][kk + 0] = l0;
                sAlo[r][kk + 1] = l1;
                sAlo[r][kk + 2] = l2;
                sAlo[r][kk + 3] = l3;
            }
            int gn = n0 + r;
            *(uint2*)&sBhi[r][kk] = *(const uint2*)(Bthi + (size_t)gn * K + k0 + kk);
            *(uint2*)&sBlo[r][kk] = *(const uint2*)(Btlo + (size_t)gn * K + k0 + kk);
        }
        __syncthreads();

        for (int ks = 0; ks < 2; ks++) {
            int colOff = ks * 16 + ((lane >> 4) << 3);
            int rsel = lane & 15;
            u32 Ah[4][4];
            u32 Al[4][4];
            u32 Bh[4][2];
            u32 Bl[4][2];
            for (int mf = 0; mf < 4; mf++) {
                ldsm4(Ah[mf], &sAhi[wm * 64 + mf * 16 + rsel][colOff]);
                ldsm4(Al[mf], &sAlo[wm * 64 + mf * 16 + rsel][colOff]);
            }
            for (int p = 0; p < 2; p++) {
                u32 t[4];
                ldsm4(t, &sBhi[wn * 32 + p * 16 + rsel][colOff]);
                Bh[2 * p][0] = t[0];
                Bh[2 * p][1] = t[2];
                Bh[2 * p + 1][0] = t[1];
                Bh[2 * p + 1][1] = t[3];
                ldsm4(t, &sBlo[wn * 32 + p * 16 + rsel][colOff]);
                Bl[2 * p][0] = t[0];
                Bl[2 * p][1] = t[2];
                Bl[2 * p + 1][0] = t[1];
                Bl[2 * p + 1][1] = t[3];
            }
            for (int mf = 0; mf < 4; mf++) {
                for (int nf = 0; nf < 4; nf++) {
                    mma16816(acc[mf][nf], Ah[mf], Bh[nf]);
                    mma16816(acc[mf][nf], Ah[mf], Bl[nf]);
                    mma16816(acc[mf][nf], Al[mf], Bh[nf]);
                }
            }
        }
        __syncthreads();
    }

    for (int mf = 0; mf < 4; mf++) {
        int r0 = m0 + wm * 64 + mf * 16 + (lane >> 2);
        for (int nf = 0; nf < 4; nf++) {
            int cb = n0 + wn * 32 + nf * 8 + (lane & 3) * 2;
            if (r0 < M) {
                float2 v;
                v.x = acc[mf][nf][0];
                v.y = acc[mf][nf][1];
                *(float2*)&C[(size_t)r0 * N + cb] = v;
            }
            if (r0 + 8 < M) {
                float2 v;
                v.x = acc[mf][nf][2];
                v.y = acc[mf][nf][3];
                *(float2*)&C[(size_t)(r0 + 8) * N + cb] = v;
            }
        }
    }
}

// ---------------- layer-1 dots from x via folded WA1 -------------------------
__global__ void dots_x_kernel(const float* __restrict__ x,
                              const float* __restrict__ WA,
                              float* __restrict__ asrc,
                              float* __restrict__ adst,
                              int n_nodes)
{
    int w = (blockIdx.x * blockDim.x + threadIdx.x) >> 5;
    int lane = threadIdx.x & 31;
    if (w >= n_nodes) { return; }
    const float* xp = x + (size_t)w * 128;
    float4 xv = *(const float4*)(xp + lane * 4);
    float xs[4];
    xs[0] = xv.x; xs[1] = xv.y; xs[2] = xv.z; xs[3] = xv.w;
    float a0 = 0.0f;
    float a1 = 0.0f;
    float a2 = 0.0f;
    float a3 = 0.0f;
    for (int q = 0; q < 4; q++) {
        float4 wv = *(const float4*)(WA + (size_t)(lane * 4 + q) * 4);
        a0 += xs[q] * wv.x;
        a1 += xs[q] * wv.y;
        a2 += xs[q] * wv.z;
        a3 += xs[q] * wv.w;
    }
    for (int o = 16; o > 0; o >>= 1) {
        a0 += __shfl_xor_sync(0xffffffffu, a0, o);
        a1 += __shfl_xor_sync(0xffffffffu, a1, o);
        a2 += __shfl_xor_sync(0xffffffffu, a2, o);
        a3 += __shfl_xor_sync(0xffffffffu, a3, o);
    }
    if (lane == 0) {
        asrc[2 * w] = a0;
        asrc[2 * w + 1] = a1;
        adst[2 * w] = a2;
        adst[2 * w + 1] = a3;
    }
}

// ---------------- layer-2 dots (reads H2) -------------------------------------
template <int C>
__global__ void attn_dots_kernel(const float* __restrict__ h,
                                 const float* __restrict__ attS,
                                 const float* __restrict__ attD,
                                 float* __restrict__ asrc,
                                 float* __restrict__ adst,
                                 int n_nodes)
{
    int w = (blockIdx.x * blockDim.x + threadIdx.x) >> 5;
    int lane = threadIdx.x & 31;
    if (w >= n_nodes) { return; }
    const float* hp = h + (size_t)w * 2 * C;
    float s0 = 0.0f;
    float d0 = 0.0f;
    float s1 = 0.0f;
    float d1 = 0.0f;
    for (int c = lane; c < C; c += 32) {
        float h0 = hp[c];
        float h1 = hp[C + c];
        s0 += h0 * attS[c];
        d0 += h0 * attD[c];
        s1 += h1 * attS[C + c];
        d1 += h1 * attD[C + c];
    }
    for (int o = 16; o > 0; o >>= 1) {
        s0 += __shfl_xor_sync(0xffffffffu, s0, o);
        d0 += __shfl_xor_sync(0xffffffffu, d0, o);
        s1 += __shfl_xor_sync(0xffffffffu, s1, o);
        d1 += __shfl_xor_sync(0xffffffffu, d1, o);
    }
    if (lane == 0) {
        asrc[2 * w] = s0;
        asrc[2 * w + 1] = s1;
        adst[2 * w] = d0;
        adst[2 * w + 1] = d1;
    }
}

__device__ __forceinline__ float lrelu(float x)
{
    return (x > 0.0f) ? x : 0.2f * x;
}

// online softmax per-lane update
__device__ __forceinline__ void online_upd(float e, float& m, float& s)
{
    if (e > m) {
        s = s * __expf(m - e) + 1.0f;
        m = e;
    } else {
        s += __expf(e - m);
    }
}

// ---------------- layer-1 aggregation (ELU + bf16 split out) -----------------
__global__ void gat_agg_l1_kernel(const float* __restrict__ asrc,
                                  const float* __restrict__ adst,
                                  const float* __restrict__ h,
                                  const float* __restrict__ bias,
                                  __nv_bfloat16* __restrict__ ohi,
                                  __nv_bfloat16* __restrict__ olo,
                                  int n_nodes)
{
    int w = (blockIdx.x * blockDim.x + threadIdx.x) >> 5;
    int lane = threadIdx.x & 31;
    if (w >= n_nodes) { return; }
    int s0 = g_off[w];
    int s1 = g_off[w + 1];
    float ad0 = adst[2 * w];
    float ad1 = adst[2 * w + 1];

    // single online pass: per-lane running (max, sum)
    float m0 = -1e30f;
    float m1 = -1e30f;
    float sm0 = 0.0f;
    float sm1 = 0.0f;
    for (int i = s0 + lane; i < s1; i += 32) {
        int s = g_srcList[i];
        float e0 = lrelu(asrc[2 * s] + ad0);
        float e1 = lrelu(asrc[2 * s + 1] + ad1);
        online_upd(e0, m0, sm0);
        online_upd(e1, m1, sm1);
    }
    float M0 = m0;
    float M1 = m1;
    for (int o = 16; o > 0; o >>= 1) {
        M0 = fmaxf(M0, __shfl_xor_sync(0xffffffffu, M0, o));
        M1 = fmaxf(M1, __shfl_xor_sync(0xffffffffu, M1, o));
    }
    float t0 = sm0 * __expf(m0 - M0);
    float t1 = sm1 * __expf(m1 - M1);
    for (int o = 16; o > 0; o >>= 1) {
        t0 += __shfl_xor_sync(0xffffffffu, t0, o);
        t1 += __shfl_xor_sync(0xffffffffu, t1, o);
    }
    float inv0 = 1.0f / (t0 + 1e-16f);
    float inv1 = 1.0f / (t1 + 1e-16f);
    m0 = M0;
    m1 = M1;

    // weighted gather, unrolled by 2 for MLP
    float acc0[4];
    float acc1[4];
    for (int v = 0; v < 4; v++) { acc0[v] = 0.0f; acc1[v] = 0.0f; }
    int i = s0;
    for (; i + 2 <= s1; i += 2) {
        int sa = g_srcList[i];
        int sb = g_srcList[i + 1];
        float wa0 = __expf(lrelu(asrc[2 * sa] + ad0) - m0) * inv0;
        float wa1 = __expf(lrelu(asrc[2 * sa + 1] + ad1) - m1) * inv1;
        float wb0 = __expf(lrelu(asrc[2 * sb] + ad0) - m0) * inv0;
        float wb1 = __expf(lrelu(asrc[2 * sb + 1] + ad1) - m1) * inv1;
        const float* ha = h + (size_t)sa * 256;
        const float* hb = h + (size_t)sb * 256;
        float4 a0 = *(const float4*)(ha + lane * 4);
        float4 a1 = *(const float4*)(ha + 128 + lane * 4);
        float4 b0 = *(const float4*)(hb + lane * 4);
        float4 b1 = *(const float4*)(hb + 128 + lane * 4);
        acc0[0] += wa0 * a0.x + wb0 * b0.x;
        acc0[1] += wa0 * a0.y + wb0 * b0.y;
        acc0[2] += wa0 * a0.z + wb0 * b0.z;
        acc0[3] += wa0 * a0.w + wb0 * b0.w;
        acc1[0] += wa1 * a1.x + wb1 * b1.x;
        acc1[1] += wa1 * a1.y + wb1 * b1.y;
        acc1[2] += wa1 * a1.z + wb1 * b1.z;
        acc1[3] += wa1 * a1.w + wb1 * b1.w;
    }
    if (i < s1) {
        int sa = g_srcList[i];
        float wa0 = __expf(lrelu(asrc[2 * sa] + ad0) - m0) * inv0;
        float wa1 = __expf(lrelu(asrc[2 * sa + 1] + ad1) - m1) * inv1;
        const float* ha = h + (size_t)sa * 256;
        float4 a0 = *(const float4*)(ha + lane * 4);
        float4 a1 = *(const float4*)(ha + 128 + lane * 4);
        acc0[0] += wa0 * a0.x;
        acc0[1] += wa0 * a0.y;
        acc0[2] += wa0 * a0.z;
        acc0[3] += wa0 * a0.w;
        acc1[0] += wa1 * a1.x;
        acc1[1] += wa1 * a1.y;
        acc1[2] += wa1 * a1.z;
        acc1[3] += wa1 * a1.w;
    }

    size_t base = (size_t)w * 256;
    for (int v = 0; v < 4; v++) {
        int c0 = lane * 4 + v;
        float r0 = acc0[v] + bias[c0];
        float r1 = acc1[v] + bias[128 + c0];
        r0 = (r0 > 0.0f) ? r0 : expm1f(r0);
        r1 = (r1 > 0.0f) ? r1 : expm1f(r1);
        __nv_bfloat16 h0 = __float2bfloat16(r0);
        __nv_bfloat16 h1 = __float2bfloat16(r1);
        ohi[base + c0] = h0;
        olo[base + c0] = __float2bfloat16(r0 - __bfloat162float(h0));
        ohi[base + 128 + c0] = h1;
        olo[base + 128 + c0] = __float2bfloat16(r1 - __bfloat162float(h1));
    }
}

// ---------------- layer-2 aggregation (mu | logstd, fp32 out) ----------------
__global__ void gat_agg_l2_kernel(const float* __restrict__ asrc,
                                  const float* __restrict__ adst,
                                  const float* __restrict__ h,
                                  const float* __restrict__ bmu,
                                  const float* __restrict__ bls,
                                  float* __restrict__ out_mu,
                                  float* __restrict__ out_ls,
                                  int n_nodes)
{
    int w = (blockIdx.x * blockDim.x + threadIdx.x) >> 5;
    int lane = threadIdx.x & 31;
    if (w >= n_nodes) { return; }
    int s0 = g_off[w];
    int s1 = g_off[w + 1];
    float ad0 = adst[2 * w];
    float ad1 = adst[2 * w + 1];

    float m0 = -1e30f;
    float m1 = -1e30f;
    float sm0 = 0.0f;
    float sm1 = 0.0f;
    for (int i = s0 + lane; i < s1; i += 32) {
        int s = g_srcList[i];
        float e0 = lrelu(asrc[2 * s] + ad0);
        float e1 = lrelu(asrc[2 * s + 1] + ad1);
        online_upd(e0, m0, sm0);
        online_upd(e1, m1, sm1);
    }
    float M0 = m0;
    float M1 = m1;
    for (int o = 16; o > 0; o >>= 1) {
        M0 = fmaxf(M0, __shfl_xor_sync(0xffffffffu, M0, o));
        M1 = fmaxf(M1, __shfl_xor_sync(0xffffffffu, M1, o));
    }
    float t0 = sm0 * __expf(m0 - M0);
    float t1 = sm1 * __expf(m1 - M1);
    for (int o = 16; o > 0; o >>= 1) {
        t0 += __shfl_xor_sync(0xffffffffu, t0, o);
        t1 += __shfl_xor_sync(0xffffffffu, t1, o);
    }
    float inv0 = 1.0f / (t0 + 1e-16f);
    float inv1 = 1.0f / (t1 + 1e-16f);
    m0 = M0;
    m1 = M1;

    float a00 = 0.0f;
    float a01 = 0.0f;
    float a10 = 0.0f;
    float a11 = 0.0f;
    int i = s0;
    for (; i + 2 <= s1; i += 2) {
        int sa = g_srcList[i];
        int sb = g_srcList[i + 1];
        float wa0 = __expf(lrelu(asrc[2 * sa] + ad0) - m0) * inv0;
        float wa1 = __expf(lrelu(asrc[2 * sa + 1] + ad1) - m1) * inv1;
        float wb0 = __expf(lrelu(asrc[2 * sb] + ad0) - m0) * inv0;
        float wb1 = __expf(lrelu(asrc[2 * sb + 1] + ad1) - m1) * inv1;
        const float* ha = h + (size_t)sa * 128;
        const float* hb = h + (size_t)sb * 128;
        float2 va0 = *(const float2*)(ha + lane * 2);
        float2 va1 = *(const float2*)(ha + 64 + lane * 2);
        float2 vb0 = *(const float2*)(hb + lane * 2);
        float2 vb1 = *(const float2*)(hb + 64 + lane * 2);
        a00 += wa0 * va0.x + wb0 * vb0.x;
        a01 += wa0 * va0.y + wb0 * vb0.y;
        a10 += wa1 * va1.x + wb1 * vb1.x;
        a11 += wa1 * va1.y + wb1 * vb1.y;
    }
    if (i < s1) {
        int sa = g_srcList[i];
        float wa0 = __expf(lrelu(asrc[2 * sa] + ad0) - m0) * inv0;
        float wa1 = __expf(lrelu(asrc[2 * sa + 1] + ad1) - m1) * inv1;
        const float* ha = h + (size_t)sa * 128;
        float2 va0 = *(const float2*)(ha + lane * 2);
        float2 va1 = *(const float2*)(ha + 64 + lane * 2);
        a00 += wa0 * va0.x;
        a01 += wa0 * va0.y;
        a10 += wa1 * va1.x;
        a11 += wa1 * va1.y;
    }
    float* o0 = out_mu + (size_t)w * 64 + lane * 2;
    float* o1 = out_ls + (size_t)w * 64 + lane * 2;
    o0[0] = a00 + bmu[lane * 2];
    o0[1] = a01 + bmu[lane * 2 + 1];
    o1[0] = a10 + bls[lane * 2];
    o1[1] = a11 + bls[lane * 2 + 1];
}

// ---------------- host launch ------------------------------------------------
static void* symaddr(const void* s)
{
    void* p = nullptr;
    cudaGetSymbolAddress(&p, s);
    return p;
}

extern "C" void kernel_launch(void* const* d_in, const int* in_sizes, int n_in,
                              void* d_out, int out_size)
{
    const float* x      = (const float*)d_in[0];
    const int*   ei     = (const int*)d_in[1];
    const float* W1     = (const float*)d_in[2];
    const float* attS1  = (const float*)d_in[3];
    const float* attD1  = (const float*)d_in[4];
    const float* b1     = (const float*)d_in[5];
    const float* Wmu    = (const float*)d_in[6];
    const float* attSmu = (const float*)d_in[7];
    const float* attDmu = (const float*)d_in[8];
    const float* bmu    = (const float*)d_in[9];
    const float* Wls    = (const float*)d_in[10];
    const float* attSls = (const float*)d_in[11];
    const float* attDls = (const float*)d_in[12];
    const float* bls    = (const float*)d_in[13];
    float* out = (float*)d_out;

    float* H1 = (float*)symaddr(g_H1);
    float* H2 = (float*)symaddr(g_H2);
    __nv_bfloat16* O1hi  = (__nv_bfloat16*)symaddr(g_O1hi);
    __nv_bfloat16* O1lo  = (__nv_bfloat16*)symaddr(g_O1lo);
    __nv_bfloat16* B1thi = (__nv_bfloat16*)symaddr(g_B1thi);
    __nv_bfloat16* B1tlo = (__nv_bfloat16*)symaddr(g_B1tlo);
    __nv_bfloat16* B2thi = (__nv_bfloat16*)symaddr(g_B2thi);
    __nv_bfloat16* B2tlo = (__nv_bfloat16*)symaddr(g_B2tlo);
    float* WA1 = (float*)symaddr(g_WA1);
    float* as1 = (float*)symaddr(g_as1);
    float* ad1 = (float*)symaddr(g_ad1);
    float* as2 = (float*)symaddr(g_as2);
    float* ad2 = (float*)symaddr(g_ad2);
    int* deg  = (int*)symaddr(g_deg);
    int* off  = (int*)symaddr(g_off);
    int* cur  = (int*)symaddr(g_cur);
    int* srcL = (int*)symaddr(g_srcList);
    float* S2 = (float*)symaddr(g_attS2);
    float* D2 = (float*)symaddr(g_attD2);

    const int N = NNODES;
    const int warpBlocks = (N * 32 + 255) / 256;

    // CSR build
    zero_int_kernel<<<(N + 1 + 255) / 256, 256>>>(deg, N + 1);
    hist_kernel<<<(E_TOT + 255) / 256, 256>>>(ei, deg);
    scan_kernel<<<1, 1024>>>(deg, off, cur, N, E_TOT);
    scatter_kernel<<<(E_TOT + 255) / 256, 256>>>(ei, cur, srcL);

    // weight packing / folds
    packW1_kernel<<<(256 * 128 + 255) / 256, 256>>>(W1, B1thi, B1tlo);
    packW2_kernel<<<(128 * 256 + 255) / 256, 256>>>(Wmu, Wls, B2thi, B2tlo);
    fold_att1_kernel<<<1, 512>>>(W1, attS1, attD1, WA1);
    pack_att_kernel<<<1, 64>>>(attSmu, attSls, attDmu, attDls, S2, D2);

    // layer-1 logits (independent of GEMM1)
    dots_x_kernel<<<warpBlocks, 256>>>(x, WA1, as1, ad1, N);

    // layer 1 GEMM (fp32 A, split in loader)
    dim3 grid1(2, (N + 127) / 128);
    gemm_bf16x3_kernel<false><<<grid1, 256>>>(x, (const __nv_bfloat16*)0,
                                              (const __nv_bfloat16*)0,
                                              B1thi, B1tlo, H1, N, 128, 256);
    gat_agg_l1_kernel<<<warpBlocks, 256>>>(as1, ad1, H1, b1, O1hi, O1lo, N);

    // layer 2
    dim3 grid2(1, (N + 127) / 128);
    gemm_bf16x3_kernel<true><<<grid2, 256>>>((const float*)0, O1hi, O1lo,
                                             B2thi, B2tlo, H2, N, 256, 128);
    attn_dots_kernel<64><<<warpBlocks, 256>>>(H2, S2, D2, as2, ad2, N);
    gat_agg_l2_kernel<<<warpBlocks, 256>>>(as2, ad2, H2, bmu, bls,
                                           out, out + (size_t)N * 64, N);
}

// round 11
// speedup vs baseline: 1.2427x; 1.0336x over previous
#include <cuda_runtime.h>
#include <cuda_bf16.h>
#include <stdint.h>
#include <math.h>

#define NNODES 50000
#define INCH   128
#define E_REAL 400000
#define E_TOT  450000

typedef unsigned int u32;

// ---------------- scratch (device globals) ----------------------------------
__device__ __align__(16) float g_H1[(size_t)NNODES * 256];
__device__ __align__(16) float g_H2[(size_t)NNODES * 128];
__device__ __align__(16) __nv_bfloat16 g_O1hi[(size_t)NNODES * 256];
__device__ __align__(16) __nv_bfloat16 g_O1lo[(size_t)NNODES * 256];
__device__ __align__(16) __nv_bfloat16 g_B1thi[256 * 128];
__device__ __align__(16) __nv_bfloat16 g_B1tlo[256 * 128];
__device__ __align__(16) __nv_bfloat16 g_B2thi[128 * 256];
__device__ __align__(16) __nv_bfloat16 g_B2tlo[128 * 256];
__device__ __align__(16) float g_WA1[128 * 4];
__device__ float g_as1[NNODES * 2];
__device__ float g_ad1[NNODES * 2];
__device__ float g_as2[NNODES * 2];
__device__ float g_ad2[NNODES * 2];
__device__ int   g_deg[NNODES + 1];
__device__ int   g_off[NNODES + 1];
__device__ int   g_cur[NNODES];
__device__ int   g_srcList[E_TOT];
__device__ float g_attS2[128];
__device__ float g_attD2[128];

// ---------------- small utility kernels -------------------------------------
__global__ void zero_int_kernel(int* p, int n)
{
    int i = blockIdx.x * blockDim.x + threadIdx.x;
    if (i < n) { p[i] = 0; }
}

__global__ void hist_kernel(const int* __restrict__ ei, int* __restrict__ deg)
{
    int i = blockIdx.x * blockDim.x + threadIdx.x;
    if (i >= E_TOT) { return; }
    int dst = (i < E_REAL) ? ei[E_REAL + i] : (i - E_REAL);
    atomicAdd(&deg[dst], 1);
}

__global__ void scan_kernel(const int* __restrict__ deg, int* __restrict__ off,
                            int* __restrict__ cur, int n, int total)
{
    __shared__ int warpSums[32];
    __shared__ int s_carry;
    int tid = threadIdx.x;
    int lane = tid & 31;
    int wid = tid >> 5;
    if (tid == 0) { s_carry = 0; }
    __syncthreads();
    for (int base = 0; base < n; base += 1024) {
        int idx = base + tid;
        int v = (idx < n) ? deg[idx] : 0;
        int x = v;
        for (int o = 1; o < 32; o <<= 1) {
            int y = __shfl_up_sync(0xffffffffu, x, o);
            if (lane >= o) { x += y; }
        }
        if (lane == 31) { warpSums[wid] = x; }
        __syncthreads();
        if (wid == 0) {
            int w = warpSums[lane];
            for (int o = 1; o < 32; o <<= 1) {
                int y = __shfl_up_sync(0xffffffffu, w, o);
                if (lane >= o) { w += y; }
            }
            warpSums[lane] = w;
        }
        __syncthreads();
        int blockIncl = x + ((wid > 0) ? warpSums[wid - 1] : 0);
        int excl = blockIncl - v;
        if (idx < n) {
            int val = s_carry + excl;
            off[idx] = val;
            cur[idx] = val;
        }
        __syncthreads();
        if (tid == 1023) { s_carry += blockIncl; }
        __syncthreads();
    }
    if (tid == 0) { off[n] = total; }
}

__global__ void scatter_kernel(const int* __restrict__ ei, int* __restrict__ cur,
                               int* __restrict__ srcList)
{
    int i = blockIdx.x * blockDim.x + threadIdx.x;
    if (i >= E_TOT) { return; }
    int src;
    int dst;
    if (i < E_REAL) { src = ei[i]; dst = ei[E_REAL + i]; }
    else            { src = i - E_REAL; dst = src; }
    int p = atomicAdd(&cur[dst], 1);
    srcList[p] = src;
}

__global__ void pack_att_kernel(const float* smu, const float* sls,
                                const float* dmu, const float* dls,
                                float* S, float* D)
{
    int i = threadIdx.x;  // 64 threads
    S[i] = smu[i];
    S[64 + i] = sls[i];
    D[i] = dmu[i];
    D[64 + i] = dls[i];
}

// WA1[k][j]: j=0 src h0, j=1 src h1, j=2 dst h0, j=3 dst h1
__global__ void fold_att1_kernel(const float* __restrict__ W1,
                                 const float* __restrict__ attS,
                                 const float* __restrict__ attD,
                                 float* __restrict__ WA)
{
    int t = threadIdx.x;  // 512 threads
    int k = t >> 2;
    int j = t & 3;
    int h = j & 1;
    const float* av = (j < 2) ? attS : attD;
    float s = 0.0f;
    for (int c = 0; c < 128; c++) {
        s += W1[k * 256 + h * 128 + c] * av[h * 128 + c];
    }
    WA[k * 4 + j] = s;
}

__global__ void packW1_kernel(const float* __restrict__ W1,
                              __nv_bfloat16* __restrict__ hi,
                              __nv_bfloat16* __restrict__ lo)
{
    int i = blockIdx.x * blockDim.x + threadIdx.x;
    if (i >= 256 * 128) { return; }
    int nn = i >> 7;
    int kk = i & 127;
    float v = W1[kk * 256 + nn];
    __nv_bfloat16 h = __float2bfloat16(v);
    hi[i] = h;
    lo[i] = __float2bfloat16(v - __bfloat162float(h));
}

__global__ void packW2_kernel(const float* __restrict__ Wmu,
                              const float* __restrict__ Wls,
                              __nv_bfloat16* __restrict__ hi,
                              __nv_bfloat16* __restrict__ lo)
{
    int i = blockIdx.x * blockDim.x + threadIdx.x;
    if (i >= 128 * 256) { return; }
    int nn = i >> 8;
    int kk = i & 255;
    float v = (nn < 64) ? Wmu[kk * 64 + nn] : Wls[kk * 64 + (nn - 64)];
    __nv_bfloat16 h = __float2bfloat16(v);
    hi[i] = h;
    lo[i] = __float2bfloat16(v - __bfloat162float(h));
}

// ---------------- mma.sync helpers -------------------------------------------
__device__ __forceinline__ void ldsm4(u32* r, const void* p)
{
    u32 addr = (u32)__cvta_generic_to_shared(p);
    asm volatile("ldmatrix.sync.aligned.m8n8.x4.shared.b16 {%0,%1,%2,%3}, [%4];"
        : "=r"(r[0]), "=r"(r[1]), "=r"(r[2]), "=r"(r[3]) : "r"(addr));
}

__device__ __forceinline__ void mma16816(float* c, const u32* a, const u32* b)
{
    asm volatile("mma.sync.aligned.m16n8k16.row.col.f32.bf16.bf16.f32 "
        "{%0,%1,%2,%3}, {%4,%5,%6,%7}, {%8,%9}, {%0,%1,%2,%3};"
        : "+f"(c[0]), "+f"(c[1]), "+f"(c[2]), "+f"(c[3])
        : "r"(a[0]), "r"(a[1]), "r"(a[2]), "r"(a[3]), "r"(b[0]), "r"(b[1]));
}

__device__ __forceinline__ u32 bfpack(__nv_bfloat16 a, __nv_bfloat16 b)
{
    return (u32)__bfloat16_as_ushort(a) | ((u32)__bfloat16_as_ushort(b) << 16);
}

// smem stage layout (bytes): A_hi[128][40] 10240 | A_lo 10240 | B_hi[64][40] 5120 | B_lo 5120
#define STG_AHI 0
#define STG_ALO 10240
#define STG_BHI 20480
#define STG_BLO 25600
#define STG_BYTES 30720
#define GEMM_SMEM (2 * STG_BYTES)

// ---------------- pipelined bf16x3 mma.sync GEMM ------------------------------
// C[M x ldn]; CTA computes rows [m0, m0+128), cols [n0, n0+64).
// KCH = number of 32-wide K chunks. AFP32: A fp32 (split in loader) else hi/lo.
// Bt: [ldn rows][KTOT] bf16, K contiguous.
template <int KCH, bool AFP32>
__global__ __launch_bounds__(256, 2)
void gemm_mma_kernel(const float* __restrict__ Af,
                     const __nv_bfloat16* __restrict__ Ahi_g,
                     const __nv_bfloat16* __restrict__ Alo_g,
                     const __nv_bfloat16* __restrict__ Bthi,
                     const __nv_bfloat16* __restrict__ Btlo,
                     float* __restrict__ C, int M, int ldn)
{
    extern __shared__ char smem[];
    const int KTOT = KCH * 32;
    int tid = threadIdx.x;
    int warp = tid >> 5;
    int lane = tid & 31;
    int wm = warp >> 1;                 // 0..3 (32-row slabs)
    int wn = warp & 1;                  // 0..1 (32-col slabs)
    int m0 = blockIdx.y * 128;
    int n0 = blockIdx.x * 64;

    float acc[2][4][4];
    for (int a = 0; a < 2; a++) {
        for (int b = 0; b < 4; b++) {
            for (int c = 0; c < 4; c++) { acc[a][b][c] = 0.0f; }
        }
    }

    // staging registers for one chunk
    uint4 stAh[2];
    uint4 stAl[2];
    uint4 stBh;
    uint4 stBl;

    // A chunk addressing: c = tid + 256*i (i<2) -> r = c>>2 (0..127), kk = (c&3)*8
    // B chunk addressing: r = tid>>2 (0..63), kk = (tid&3)*8

    auto load_chunk = [&](int kc) {
        for (int i = 0; i < 2; i++) {
            int c = tid + 256 * i;
            int r = c >> 2;
            int kk = (c & 3) * 8;
            int grow = m0 + r;
            uint4 vh;
            uint4 vl;
            vh.x = 0u; vh.y = 0u; vh.z = 0u; vh.w = 0u;
            vl = vh;
            if (grow < M) {
                int gcol = kc * 32 + kk;
                if (AFP32) {
                    const float* ap = Af + (size_t)grow * KTOT + gcol;
                    float4 f0 = *(const float4*)(ap);
                    float4 f1 = *(const float4*)(ap + 4);
                    float e[8];
                    e[0] = f0.x; e[1] = f0.y; e[2] = f0.z; e[3] = f0.w;
                    e[4] = f1.x; e[5] = f1.y; e[6] = f1.z; e[7] = f1.w;
                    u32 ph[4];
                    u32 pl[4];
                    for (int q = 0; q < 4; q++) {
                        __nv_bfloat16 h0 = __float2bfloat16(e[2 * q]);
                        __nv_bfloat16 h1 = __float2bfloat16(e[2 * q + 1]);
                        __nv_bfloat16 l0 = __float2bfloat16(e[2 * q] - __bfloat162float(h0));
                        __nv_bfloat16 l1 = __float2bfloat16(e[2 * q + 1] - __bfloat162float(h1));
                        ph[q] = bfpack(h0, h1);
                        pl[q] = bfpack(l0, l1);
                    }
                    vh.x = ph[0]; vh.y = ph[1]; vh.z = ph[2]; vh.w = ph[3];
                    vl.x = pl[0]; vl.y = pl[1]; vl.z = pl[2]; vl.w = pl[3];
                } else {
                    vh = *(const uint4*)(Ahi_g + (size_t)grow * KTOT + gcol);
                    vl = *(const uint4*)(Alo_g + (size_t)grow * KTOT + gcol);
                }
            }
            stAh[i] = vh;
            stAl[i] = vl;
        }
        int r = tid >> 2;
        int kk = (tid & 3) * 8;
        size_t src = (size_t)(n0 + r) * KTOT + kc * 32 + kk;
        stBh = *(const uint4*)(Bthi + src);
        stBl = *(const uint4*)(Btlo + src);
    };

    auto store_chunk = [&](int buf) {
        char* base = smem + buf * STG_BYTES;
        for (int i = 0; i < 2; i++) {
            int c = tid + 256 * i;
            int r = c >> 2;
            int kk = (c & 3) * 8;
            *(uint4*)(base + STG_AHI + r * 80 + kk * 2) = stAh[i];
            *(uint4*)(base + STG_ALO + r * 80 + kk * 2) = stAl[i];
        }
        int r = tid >> 2;
        int kk = (tid & 3) * 8;
        *(uint4*)(base + STG_BHI + r * 80 + kk * 2) = stBh;
        *(uint4*)(base + STG_BLO + r * 80 + kk * 2) = stBl;
    };

    auto compute_chunk = [&](int buf) {
        char* base = smem + buf * STG_BYTES;
        for (int ks = 0; ks < 2; ks++) {
            int colOff = ks * 16 + ((lane >> 4) << 3);
            int rsel = lane & 15;
            u32 Ah[2][4];
            u32 Al[2][4];
            u32 Bh[4][2];
            u32 Bl[4][2];
            for (int mf = 0; mf < 2; mf++) {
                int row = wm * 32 + mf * 16 + rsel;
                ldsm4(Ah[mf], base + STG_AHI + row * 80 + colOff * 2);
                ldsm4(Al[mf], base + STG_ALO + row * 80 + colOff * 2);
            }
            for (int p = 0; p < 2; p++) {
                int row = wn * 32 + p * 16 + rsel;
                u32 t[4];
                ldsm4(t, base + STG_BHI + row * 80 + colOff * 2);
                Bh[2 * p][0] = t[0];
                Bh[2 * p][1] = t[2];
                Bh[2 * p + 1][0] = t[1];
                Bh[2 * p + 1][1] = t[3];
                ldsm4(t, base + STG_BLO + row * 80 + colOff * 2);
                Bl[2 * p][0] = t[0];
                Bl[2 * p][1] = t[2];
                Bl[2 * p + 1][0] = t[1];
                Bl[2 * p + 1][1] = t[3];
            }
            for (int mf = 0; mf < 2; mf++) {
                for (int nf = 0; nf < 4; nf++) {
                    mma16816(acc[mf][nf], Ah[mf], Bh[nf]);
                    mma16816(acc[mf][nf], Ah[mf], Bl[nf]);
                    mma16816(acc[mf][nf], Al[mf], Bh[nf]);
                }
            }
        }
    };

    load_chunk(0);
    store_chunk(0);
    __syncthreads();
    for (int kc = 0; kc < KCH; kc++) {
        if (kc + 1 < KCH) { load_chunk(kc + 1); }
        compute_chunk(kc & 1);
        __syncthreads();
        if (kc + 1 < KCH) {
            store_chunk((kc + 1) & 1);
            __syncthreads();
        }
    }

    for (int mf = 0; mf < 2; mf++) {
        int r0 = m0 + wm * 32 + mf * 16 + (lane >> 2);
        for (int nf = 0; nf < 4; nf++) {
            int cb = n0 + wn * 32 + nf * 8 + (lane & 3) * 2;
            if (r0 < M) {
                float2 v;
                v.x = acc[mf][nf][0];
                v.y = acc[mf][nf][1];
                *(float2*)&C[(size_t)r0 * ldn + cb] = v;
            }
            if (r0 + 8 < M) {
                float2 v;
                v.x = acc[mf][nf][2];
                v.y = acc[mf][nf][3];
                *(float2*)&C[(size_t)(r0 + 8) * ldn + cb] = v;
            }
        }
    }
}

// ---------------- layer-1 dots from x via folded WA1 -------------------------
__global__ void dots_x_kernel(const float* __restrict__ x,
                              const float* __restrict__ WA,
                              float* __restrict__ asrc,
                              float* __restrict__ adst,
                              int n_nodes)
{
    int w = (blockIdx.x * blockDim.x + threadIdx.x) >> 5;
    int lane = threadIdx.x & 31;
    if (w >= n_nodes) { return; }
    const float* xp = x + (size_t)w * 128;
    float4 xv = *(const float4*)(xp + lane * 4);
    float xs[4];
    xs[0] = xv.x; xs[1] = xv.y; xs[2] = xv.z; xs[3] = xv.w;
    float a0 = 0.0f;
    float a1 = 0.0f;
    float a2 = 0.0f;
    float a3 = 0.0f;
    for (int q = 0; q < 4; q++) {
        float4 wv = *(const float4*)(WA + (size_t)(lane * 4 + q) * 4);
        a0 += xs[q] * wv.x;
        a1 += xs[q] * wv.y;
        a2 += xs[q] * wv.z;
        a3 += xs[q] * wv.w;
    }
    for (int o = 16; o > 0; o >>= 1) {
        a0 += __shfl_xor_sync(0xffffffffu, a0, o);
        a1 += __shfl_xor_sync(0xffffffffu, a1, o);
        a2 += __shfl_xor_sync(0xffffffffu, a2, o);
        a3 += __shfl_xor_sync(0xffffffffu, a3, o);
    }
    if (lane == 0) {
        asrc[2 * w] = a0;
        asrc[2 * w + 1] = a1;
        adst[2 * w] = a2;
        adst[2 * w + 1] = a3;
    }
}

// ---------------- layer-2 dots (reads H2) -------------------------------------
template <int C>
__global__ void attn_dots_kernel(const float* __restrict__ h,
                                 const float* __restrict__ attS,
                                 const float* __restrict__ attD,
                                 float* __restrict__ asrc,
                                 float* __restrict__ adst,
                                 int n_nodes)
{
    int w = (blockIdx.x * blockDim.x + threadIdx.x) >> 5;
    int lane = threadIdx.x & 31;
    if (w >= n_nodes) { return; }
    const float* hp = h + (size_t)w * 2 * C;
    float s0 = 0.0f;
    float d0 = 0.0f;
    float s1 = 0.0f;
    float d1 = 0.0f;
    for (int c = lane; c < C; c += 32) {
        float h0 = hp[c];
        float h1 = hp[C + c];
        s0 += h0 * attS[c];
        d0 += h0 * attD[c];
        s1 += h1 * attS[C + c];
        d1 += h1 * attD[C + c];
    }
    for (int o = 16; o > 0; o >>= 1) {
        s0 += __shfl_xor_sync(0xffffffffu, s0, o);
        d0 += __shfl_xor_sync(0xffffffffu, d0, o);
        s1 += __shfl_xor_sync(0xffffffffu, s1, o);
        d1 += __shfl_xor_sync(0xffffffffu, d1, o);
    }
    if (lane == 0) {
        asrc[2 * w] = s0;
        asrc[2 * w + 1] = s1;
        adst[2 * w] = d0;
        adst[2 * w + 1] = d1;
    }
}

__device__ __forceinline__ float lrelu(float x)
{
    return (x > 0.0f) ? x : 0.2f * x;
}

__device__ __forceinline__ void online_upd(float e, float& m, float& s)
{
    if (e > m) {
        s = s * __expf(m - e) + 1.0f;
        m = e;
    } else {
        s += __expf(e - m);
    }
}

// ---------------- layer-1 aggregation (ELU + bf16 split out) -----------------
__global__ void gat_agg_l1_kernel(const float* __restrict__ asrc,
                                  const float* __restrict__ adst,
                                  const float* __restrict__ h,
                                  const float* __restrict__ bias,
                                  __nv_bfloat16* __restrict__ ohi,
                                  __nv_bfloat16* __restrict__ olo,
                                  int n_nodes)
{
    int w = (blockIdx.x * blockDim.x + threadIdx.x) >> 5;
    int lane = threadIdx.x & 31;
    if (w >= n_nodes) { return; }
    int s0 = g_off[w];
    int s1 = g_off[w + 1];
    float ad0 = adst[2 * w];
    float ad1 = adst[2 * w + 1];

    float m0 = -1e30f;
    float m1 = -1e30f;
    float sm0 = 0.0f;
    float sm1 = 0.0f;
    for (int i = s0 + lane; i < s1; i += 32) {
        int s = g_srcList[i];
        float e0 = lrelu(asrc[2 * s] + ad0);
        float e1 = lrelu(asrc[2 * s + 1] + ad1);
        online_upd(e0, m0, sm0);
        online_upd(e1, m1, sm1);
    }
    float M0 = m0;
    float M1 = m1;
    for (int o = 16; o > 0; o >>= 1) {
        M0 = fmaxf(M0, __shfl_xor_sync(0xffffffffu, M0, o));
        M1 = fmaxf(M1, __shfl_xor_sync(0xffffffffu, M1, o));
    }
    float t0 = sm0 * __expf(m0 - M0);
    float t1 = sm1 * __expf(m1 - M1);
    for (int o = 16; o > 0; o >>= 1) {
        t0 += __shfl_xor_sync(0xffffffffu, t0, o);
        t1 += __shfl_xor_sync(0xffffffffu, t1, o);
    }
    float inv0 = 1.0f / (t0 + 1e-16f);
    float inv1 = 1.0f / (t1 + 1e-16f);
    m0 = M0;
    m1 = M1;

    float acc0[4];
    float acc1[4];
    for (int v = 0; v < 4; v++) { acc0[v] = 0.0f; acc1[v] = 0.0f; }
    int i = s0;
    for (; i + 2 <= s1; i += 2) {
        int sa = g_srcList[i];
        int sb = g_srcList[i + 1];
        float wa0 = __expf(lrelu(asrc[2 * sa] + ad0) - m0) * inv0;
        float wa1 = __expf(lrelu(asrc[2 * sa + 1] + ad1) - m1) * inv1;
        float wb0 = __expf(lrelu(asrc[2 * sb] + ad0) - m0) * inv0;
        float wb1 = __expf(lrelu(asrc[2 * sb + 1] + ad1) - m1) * inv1;
        const float* ha = h + (size_t)sa * 256;
        const float* hb = h + (size_t)sb * 256;
        float4 a0 = *(const float4*)(ha + lane * 4);
        float4 a1 = *(const float4*)(ha + 128 + lane * 4);
        float4 b0 = *(const float4*)(hb + lane * 4);
        float4 b1 = *(const float4*)(hb + 128 + lane * 4);
        acc0[0] += wa0 * a0.x + wb0 * b0.x;
        acc0[1] += wa0 * a0.y + wb0 * b0.y;
        acc0[2] += wa0 * a0.z + wb0 * b0.z;
        acc0[3] += wa0 * a0.w + wb0 * b0.w;
        acc1[0] += wa1 * a1.x + wb1 * b1.x;
        acc1[1] += wa1 * a1.y + wb1 * b1.y;
        acc1[2] += wa1 * a1.z + wb1 * b1.z;
        acc1[3] += wa1 * a1.w + wb1 * b1.w;
    }
    if (i < s1) {
        int sa = g_srcList[i];
        float wa0 = __expf(lrelu(asrc[2 * sa] + ad0) - m0) * inv0;
        float wa1 = __expf(lrelu(asrc[2 * sa + 1] + ad1) - m1) * inv1;
        const float* ha = h + (size_t)sa * 256;
        float4 a0 = *(const float4*)(ha + lane * 4);
        float4 a1 = *(const float4*)(ha + 128 + lane * 4);
        acc0[0] += wa0 * a0.x;
        acc0[1] += wa0 * a0.y;
        acc0[2] += wa0 * a0.z;
        acc0[3] += wa0 * a0.w;
        acc1[0] += wa1 * a1.x;
        acc1[1] += wa1 * a1.y;
        acc1[2] += wa1 * a1.z;
        acc1[3] += wa1 * a1.w;
    }

    size_t base = (size_t)w * 256;
    for (int v = 0; v < 4; v++) {
        int c0 = lane * 4 + v;
        float r0 = acc0[v] + bias[c0];
        float r1 = acc1[v] + bias[128 + c0];
        r0 = (r0 > 0.0f) ? r0 : expm1f(r0);
        r1 = (r1 > 0.0f) ? r1 : expm1f(r1);
        __nv_bfloat16 h0 = __float2bfloat16(r0);
        __nv_bfloat16 h1 = __float2bfloat16(r1);
        ohi[base + c0] = h0;
        olo[base + c0] = __float2bfloat16(r0 - __bfloat162float(h0));
        ohi[base + 128 + c0] = h1;
        olo[base + 128 + c0] = __float2bfloat16(r1 - __bfloat162float(h1));
    }
}

// ---------------- layer-2 aggregation (mu | logstd, fp32 out) ----------------
__global__ void gat_agg_l2_kernel(const float* __restrict__ asrc,
                                  const float* __restrict__ adst,
                                  const float* __restrict__ h,
                                  const float* __restrict__ bmu,
                                  const float* __restrict__ bls,
                                  float* __restrict__ out_mu,
                                  float* __restrict__ out_ls,
                                  int n_nodes)
{
    int w = (blockIdx.x * blockDim.x + threadIdx.x) >> 5;
    int lane = threadIdx.x & 31;
    if (w >= n_nodes) { return; }
    int s0 = g_off[w];
    int s1 = g_off[w + 1];
    float ad0 = adst[2 * w];
    float ad1 = adst[2 * w + 1];

    float m0 = -1e30f;
    float m1 = -1e30f;
    float sm0 = 0.0f;
    float sm1 = 0.0f;
    for (int i = s0 + lane; i < s1; i += 32) {
        int s = g_srcList[i];
        float e0 = lrelu(asrc[2 * s] + ad0);
        float e1 = lrelu(asrc[2 * s + 1] + ad1);
        online_upd(e0, m0, sm0);
        online_upd(e1, m1, sm1);
    }
    float M0 = m0;
    float M1 = m1;
    for (int o = 16; o > 0; o >>= 1) {
        M0 = fmaxf(M0, __shfl_xor_sync(0xffffffffu, M0, o));
        M1 = fmaxf(M1, __shfl_xor_sync(0xffffffffu, M1, o));
    }
    float t0 = sm0 * __expf(m0 - M0);
    float t1 = sm1 * __expf(m1 - M1);
    for (int o = 16; o > 0; o >>= 1) {
        t0 += __shfl_xor_sync(0xffffffffu, t0, o);
        t1 += __shfl_xor_sync(0xffffffffu, t1, o);
    }
    float inv0 = 1.0f / (t0 + 1e-16f);
    float inv1 = 1.0f / (t1 + 1e-16f);
    m0 = M0;
    m1 = M1;

    float a00 = 0.0f;
    float a01 = 0.0f;
    float a10 = 0.0f;
    float a11 = 0.0f;
    int i = s0;
    for (; i + 2 <= s1; i += 2) {
        int sa = g_srcList[i];
        int sb = g_srcList[i + 1];
        float wa0 = __expf(lrelu(asrc[2 * sa] + ad0) - m0) * inv0;
        float wa1 = __expf(lrelu(asrc[2 * sa + 1] + ad1) - m1) * inv1;
        float wb0 = __expf(lrelu(asrc[2 * sb] + ad0) - m0) * inv0;
        float wb1 = __expf(lrelu(asrc[2 * sb + 1] + ad1) - m1) * inv1;
        const float* ha = h + (size_t)sa * 128;
        const float* hb = h + (size_t)sb * 128;
        float2 va0 = *(const float2*)(ha + lane * 2);
        float2 va1 = *(const float2*)(ha + 64 + lane * 2);
        float2 vb0 = *(const float2*)(hb + lane * 2);
        float2 vb1 = *(const float2*)(hb + 64 + lane * 2);
        a00 += wa0 * va0.x + wb0 * vb0.x;
        a01 += wa0 * va0.y + wb0 * vb0.y;
        a10 += wa1 * va1.x + wb1 * vb1.x;
        a11 += wa1 * va1.y + wb1 * vb1.y;
    }
    if (i < s1) {
        int sa = g_srcList[i];
        float wa0 = __expf(lrelu(asrc[2 * sa] + ad0) - m0) * inv0;
        float wa1 = __expf(lrelu(asrc[2 * sa + 1] + ad1) - m1) * inv1;
        const float* ha = h + (size_t)sa * 128;
        float2 va0 = *(const float2*)(ha + lane * 2);
        float2 va1 = *(const float2*)(ha + 64 + lane * 2);
        a00 += wa0 * va0.x;
        a01 += wa0 * va0.y;
        a10 += wa1 * va1.x;
        a11 += wa1 * va1.y;
    }
    float* o0 = out_mu + (size_t)w * 64 + lane * 2;
    float* o1 = out_ls + (size_t)w * 64 + lane * 2;
    o0[0] = a00 + bmu[lane * 2];
    o0[1] = a01 + bmu[lane * 2 + 1];
    o1[0] = a10 + bls[lane * 2];
    o1[1] = a11 + bls[lane * 2 + 1];
}

// ---------------- host launch ------------------------------------------------
static void* symaddr(const void* s)
{
    void* p = nullptr;
    cudaGetSymbolAddress(&p, s);
    return p;
}

extern "C" void kernel_launch(void* const* d_in, const int* in_sizes, int n_in,
                              void* d_out, int out_size)
{
    const float* x      = (const float*)d_in[0];
    const int*   ei     = (const int*)d_in[1];
    const float* W1     = (const float*)d_in[2];
    const float* attS1  = (const float*)d_in[3];
    const float* attD1  = (const float*)d_in[4];
    const float* b1     = (const float*)d_in[5];
    const float* Wmu    = (const float*)d_in[6];
    const float* attSmu = (const float*)d_in[7];
    const float* attDmu = (const float*)d_in[8];
    const float* bmu    = (const float*)d_in[9];
    const float* Wls    = (const float*)d_in[10];
    const float* attSls = (const float*)d_in[11];
    const float* attDls = (const float*)d_in[12];
    const float* bls    = (const float*)d_in[13];
    float* out = (float*)d_out;

    float* H1 = (float*)symaddr(g_H1);
    float* H2 = (float*)symaddr(g_H2);
    __nv_bfloat16* O1hi  = (__nv_bfloat16*)symaddr(g_O1hi);
    __nv_bfloat16* O1lo  = (__nv_bfloat16*)symaddr(g_O1lo);
    __nv_bfloat16* B1thi = (__nv_bfloat16*)symaddr(g_B1thi);
    __nv_bfloat16* B1tlo = (__nv_bfloat16*)symaddr(g_B1tlo);
    __nv_bfloat16* B2thi = (__nv_bfloat16*)symaddr(g_B2thi);
    __nv_bfloat16* B2tlo = (__nv_bfloat16*)symaddr(g_B2tlo);
    float* WA1 = (float*)symaddr(g_WA1);
    float* as1 = (float*)symaddr(g_as1);
    float* ad1 = (float*)symaddr(g_ad1);
    float* as2 = (float*)symaddr(g_as2);
    float* ad2 = (float*)symaddr(g_ad2);
    int* deg  = (int*)symaddr(g_deg);
    int* off  = (int*)symaddr(g_off);
    int* cur  = (int*)symaddr(g_cur);
    int* srcL = (int*)symaddr(g_srcList);
    float* S2 = (float*)symaddr(g_attS2);
    float* D2 = (float*)symaddr(g_attD2);

    const int N = NNODES;
    const int warpBlocks = (N * 32 + 255) / 256;
    const int mtiles = (N + 127) / 128;  // 391

    cudaFuncSetAttribute(gemm_mma_kernel<4, true>,
                         cudaFuncAttributeMaxDynamicSharedMemorySize, GEMM_SMEM);
    cudaFuncSetAttribute(gemm_mma_kernel<8, false>,
                         cudaFuncAttributeMaxDynamicSharedMemorySize, GEMM_SMEM);

    // --- launches 1..5 (prep; gemm1 lands at slot 6 for ncu -s 5 -c 1) ------
    packW1_kernel<<<(256 * 128 + 255) / 256, 256>>>(W1, B1thi, B1tlo);
    packW2_kernel<<<(128 * 256 + 255) / 256, 256>>>(Wmu, Wls, B2thi, B2tlo);
    fold_att1_kernel<<<1, 512>>>(W1, attS1, attD1, WA1);
    pack_att_kernel<<<1, 64>>>(attSmu, attSls, attDmu, attDls, S2, D2);
    dots_x_kernel<<<warpBlocks, 256>>>(x, WA1, as1, ad1, N);

    // --- launch 6: layer-1 GEMM: H1 = x @ W1 (N=256 -> 4 col-tiles) ---------
    gemm_mma_kernel<4, true><<<dim3(4, mtiles), 256, GEMM_SMEM>>>(
        x, (const __nv_bfloat16*)0, (const __nv_bfloat16*)0,
        B1thi, B1tlo, H1, N, 256);

    // --- CSR build (needed before aggregation only) -------------------------
    zero_int_kernel<<<(N + 1 + 255) / 256, 256>>>(deg, N + 1);
    hist_kernel<<<(E_TOT + 255) / 256, 256>>>(ei, deg);
    scan_kernel<<<1, 1024>>>(deg, off, cur, N, E_TOT);
    scatter_kernel<<<(E_TOT + 255) / 256, 256>>>(ei, cur, srcL);

    gat_agg_l1_kernel<<<warpBlocks, 256>>>(as1, ad1, H1, b1, O1hi, O1lo, N);

    // --- layer 2 ------------------------------------------------------------
    gemm_mma_kernel<8, false><<<dim3(2, mtiles), 256, GEMM_SMEM>>>(
        (const float*)0, O1hi, O1lo, B2thi, B2tlo, H2, N, 128);
    attn_dots_kernel<64><<<warpBlocks, 256>>>(H2, S2, D2, as2, ad2, N);
    gat_agg_l2_kernel<<<warpBlocks, 256>>>(as2, ad2, H2, bmu, bls,
                                           out, out + (size_t)N * 64, N);
}

// round 12
// speedup vs baseline: 1.2771x; 1.0277x over previous
#include <cuda_runtime.h>
#include <cuda_bf16.h>
#include <stdint.h>
#include <math.h>

#define NNODES 50000
#define INCH   128
#define E_REAL 400000
#define E_TOT  450000

typedef unsigned int u32;

// ---------------- scratch (device globals) ----------------------------------
__device__ __align__(16) float g_H1[(size_t)NNODES * 256];
__device__ __align__(16) float g_H2[(size_t)NNODES * 128];
__device__ __align__(16) __nv_bfloat16 g_O1hi[(size_t)NNODES * 256];
__device__ __align__(16) __nv_bfloat16 g_O1lo[(size_t)NNODES * 256];
__device__ __align__(16) __nv_bfloat16 g_B1thi[256 * 128];
__device__ __align__(16) __nv_bfloat16 g_B1tlo[256 * 128];
__device__ __align__(16) __nv_bfloat16 g_B2thi[128 * 256];
__device__ __align__(16) __nv_bfloat16 g_B2tlo[128 * 256];
__device__ __align__(16) float g_WA1[128 * 4];
__device__ float g_as1[NNODES * 2];
__device__ float g_ad1[NNODES * 2];
__device__ float g_as2[NNODES * 2];
__device__ float g_ad2[NNODES * 2];
__device__ int   g_deg[NNODES + 1];
__device__ int   g_off[NNODES + 1];
__device__ int   g_cur[NNODES];
__device__ int   g_srcList[E_TOT];
__device__ float g_attS2[128];
__device__ float g_attD2[128];

// ---------------- small utility kernels -------------------------------------
__global__ void zero_int_kernel(int* p, int n)
{
    int i = blockIdx.x * blockDim.x + threadIdx.x;
    if (i < n) { p[i] = 0; }
}

__global__ void hist_kernel(const int* __restrict__ ei, int* __restrict__ deg)
{
    int i = blockIdx.x * blockDim.x + threadIdx.x;
    if (i >= E_TOT) { return; }
    int dst = (i < E_REAL) ? ei[E_REAL + i] : (i - E_REAL);
    atomicAdd(&deg[dst], 1);
}

__global__ void scan_kernel(const int* __restrict__ deg, int* __restrict__ off,
                            int* __restrict__ cur, int n, int total)
{
    __shared__ int warpSums[32];
    __shared__ int s_carry;
    int tid = threadIdx.x;
    int lane = tid & 31;
    int wid = tid >> 5;
    if (tid == 0) { s_carry = 0; }
    __syncthreads();
    for (int base = 0; base < n; base += 1024) {
        int idx = base + tid;
        int v = (idx < n) ? deg[idx] : 0;
        int x = v;
        for (int o = 1; o < 32; o <<= 1) {
            int y = __shfl_up_sync(0xffffffffu, x, o);
            if (lane >= o) { x += y; }
        }
        if (lane == 31) { warpSums[wid] = x; }
        __syncthreads();
        if (wid == 0) {
            int w = warpSums[lane];
            for (int o = 1; o < 32; o <<= 1) {
                int y = __shfl_up_sync(0xffffffffu, w, o);
                if (lane >= o) { w += y; }
            }
            warpSums[lane] = w;
        }
        __syncthreads();
        int blockIncl = x + ((wid > 0) ? warpSums[wid - 1] : 0);
        int excl = blockIncl - v;
        if (idx < n) {
            int val = s_carry + excl;
            off[idx] = val;
            cur[idx] = val;
        }
        __syncthreads();
        if (tid == 1023) { s_carry += blockIncl; }
        __syncthreads();
    }
    if (tid == 0) { off[n] = total; }
}

__global__ void scatter_kernel(const int* __restrict__ ei, int* __restrict__ cur,
                               int* __restrict__ srcList)
{
    int i = blockIdx.x * blockDim.x + threadIdx.x;
    if (i >= E_TOT) { return; }
    int src;
    int dst;
    if (i < E_REAL) { src = ei[i]; dst = ei[E_REAL + i]; }
    else            { src = i - E_REAL; dst = src; }
    int p = atomicAdd(&cur[dst], 1);
    srcList[p] = src;
}

// block 0-1: fold WA1; block 2: pack att2 vectors; blocks 3+: zero as2/ad2
__global__ void prep_misc_kernel(const float* __restrict__ W1,
                                 const float* __restrict__ attS1,
                                 const float* __restrict__ attD1,
                                 const float* __restrict__ smu,
                                 const float* __restrict__ sls,
                                 const float* __restrict__ dmu,
                                 const float* __restrict__ dls,
                                 float* __restrict__ WA,
                                 float* __restrict__ S,
                                 float* __restrict__ D,
                                 float* __restrict__ as2,
                                 float* __restrict__ ad2)
{
    int b = blockIdx.x;
    int t = threadIdx.x;
    if (b < 2) {
        int it = b * 256 + t;      // 0..511
        int k = it >> 2;
        int j = it & 3;
        int h = j & 1;
        const float* av = (j < 2) ? attS1 : attD1;
        float s = 0.0f;
        for (int c = 0; c < 128; c++) {
            s += W1[k * 256 + h * 128 + c] * av[h * 128 + c];
        }
        WA[k * 4 + j] = s;
    } else if (b == 2) {
        if (t < 64) {
            S[t] = smu[t];
            S[64 + t] = sls[t];
            D[t] = dmu[t];
            D[64 + t] = dls[t];
        }
    } else {
        int i = (b - 3) * 256 + t;
        if (i < NNODES * 2) {
            as2[i] = 0.0f;
            ad2[i] = 0.0f;
        }
    }
}

__global__ void packW1_kernel(const float* __restrict__ W1,
                              __nv_bfloat16* __restrict__ hi,
                              __nv_bfloat16* __restrict__ lo)
{
    int i = blockIdx.x * blockDim.x + threadIdx.x;
    if (i >= 256 * 128) { return; }
    int nn = i >> 7;
    int kk = i & 127;
    float v = W1[kk * 256 + nn];
    __nv_bfloat16 h = __float2bfloat16(v);
    hi[i] = h;
    lo[i] = __float2bfloat16(v - __bfloat162float(h));
}

__global__ void packW2_kernel(const float* __restrict__ Wmu,
                              const float* __restrict__ Wls,
                              __nv_bfloat16* __restrict__ hi,
                              __nv_bfloat16* __restrict__ lo)
{
    int i = blockIdx.x * blockDim.x + threadIdx.x;
    if (i >= 128 * 256) { return; }
    int nn = i >> 8;
    int kk = i & 255;
    float v = (nn < 64) ? Wmu[kk * 64 + nn] : Wls[kk * 64 + (nn - 64)];
    __nv_bfloat16 h = __float2bfloat16(v);
    hi[i] = h;
    lo[i] = __float2bfloat16(v - __bfloat162float(h));
}

// ---------------- mma.sync helpers -------------------------------------------
__device__ __forceinline__ void ldsm4(u32* r, const void* p)
{
    u32 addr = (u32)__cvta_generic_to_shared(p);
    asm volatile("ldmatrix.sync.aligned.m8n8.x4.shared.b16 {%0,%1,%2,%3}, [%4];"
        : "=r"(r[0]), "=r"(r[1]), "=r"(r[2]), "=r"(r[3]) : "r"(addr));
}

__device__ __forceinline__ void mma16816(float* c, const u32* a, const u32* b)
{
    asm volatile("mma.sync.aligned.m16n8k16.row.col.f32.bf16.bf16.f32 "
        "{%0,%1,%2,%3}, {%4,%5,%6,%7}, {%8,%9}, {%0,%1,%2,%3};"
        : "+f"(c[0]), "+f"(c[1]), "+f"(c[2]), "+f"(c[3])
        : "r"(a[0]), "r"(a[1]), "r"(a[2]), "r"(a[3]), "r"(b[0]), "r"(b[1]));
}

__device__ __forceinline__ u32 bfpack(__nv_bfloat16 a, __nv_bfloat16 b)
{
    return (u32)__bfloat16_as_ushort(a) | ((u32)__bfloat16_as_ushort(b) << 16);
}

// smem stage layout (bytes): A_hi[128][40] 10240 | A_lo 10240 | B_hi[64][40] 5120 | B_lo 5120
#define STG_AHI 0
#define STG_ALO 10240
#define STG_BHI 20480
#define STG_BLO 25600
#define STG_BYTES 30720
#define GEMM_SMEM (2 * STG_BYTES)

// ---------------- pipelined bf16x3 mma.sync GEMM ------------------------------
// C[M x ldn]; CTA computes rows [m0, m0+128), cols [n0, n0+64).
// KCH 32-wide K chunks. AFP32: A fp32 (split in loader) else bf16 hi/lo.
// DOTS: fuse attention-dot partials (requires ldn==128; head = n0>>6).
template <int KCH, bool AFP32, bool DOTS>
__global__ __launch_bounds__(256, 2)
void gemm_mma_kernel(const float* __restrict__ Af,
                     const __nv_bfloat16* __restrict__ Ahi_g,
                     const __nv_bfloat16* __restrict__ Alo_g,
                     const __nv_bfloat16* __restrict__ Bthi,
                     const __nv_bfloat16* __restrict__ Btlo,
                     float* __restrict__ C, int M, int ldn,
                     const float* __restrict__ Sv,
                     const float* __restrict__ Dv,
                     float* __restrict__ asrc,
                     float* __restrict__ adst)
{
    extern __shared__ char smem[];
    const int KTOT = KCH * 32;
    int tid = threadIdx.x;
    int warp = tid >> 5;
    int lane = tid & 31;
    int wm = warp >> 1;                 // 0..3 (32-row slabs)
    int wn = warp & 1;                  // 0..1 (32-col slabs)
    int m0 = blockIdx.y * 128;
    int n0 = blockIdx.x * 64;

    float acc[2][4][4];
    for (int a = 0; a < 2; a++) {
        for (int b = 0; b < 4; b++) {
            for (int c = 0; c < 4; c++) { acc[a][b][c] = 0.0f; }
        }
    }

    uint4 stAh[2];
    uint4 stAl[2];
    uint4 stBh;
    uint4 stBl;

    auto load_chunk = [&](int kc) {
        for (int i = 0; i < 2; i++) {
            int c = tid + 256 * i;
            int r = c >> 2;
            int kk = (c & 3) * 8;
            int grow = m0 + r;
            uint4 vh;
            uint4 vl;
            vh.x = 0u; vh.y = 0u; vh.z = 0u; vh.w = 0u;
            vl = vh;
            if (grow < M) {
                int gcol = kc * 32 + kk;
                if (AFP32) {
                    const float* ap = Af + (size_t)grow * KTOT + gcol;
                    float4 f0 = *(const float4*)(ap);
                    float4 f1 = *(const float4*)(ap + 4);
                    float e[8];
                    e[0] = f0.x; e[1] = f0.y; e[2] = f0.z; e[3] = f0.w;
                    e[4] = f1.x; e[5] = f1.y; e[6] = f1.z; e[7] = f1.w;
                    u32 ph[4];
                    u32 pl[4];
                    for (int q = 0; q < 4; q++) {
                        __nv_bfloat16 h0 = __float2bfloat16(e[2 * q]);
                        __nv_bfloat16 h1 = __float2bfloat16(e[2 * q + 1]);
                        __nv_bfloat16 l0 = __float2bfloat16(e[2 * q] - __bfloat162float(h0));
                        __nv_bfloat16 l1 = __float2bfloat16(e[2 * q + 1] - __bfloat162float(h1));
                        ph[q] = bfpack(h0, h1);
                        pl[q] = bfpack(l0, l1);
                    }
                    vh.x = ph[0]; vh.y = ph[1]; vh.z = ph[2]; vh.w = ph[3];
                    vl.x = pl[0]; vl.y = pl[1]; vl.z = pl[2]; vl.w = pl[3];
                } else {
                    vh = *(const uint4*)(Ahi_g + (size_t)grow * KTOT + gcol);
                    vl = *(const uint4*)(Alo_g + (size_t)grow * KTOT + gcol);
                }
            }
            stAh[i] = vh;
            stAl[i] = vl;
        }
        int r = tid >> 2;
        int kk = (tid & 3) * 8;
        size_t src = (size_t)(n0 + r) * KTOT + kc * 32 + kk;
        stBh = *(const uint4*)(Bthi + src);
        stBl = *(const uint4*)(Btlo + src);
    };

    auto store_chunk = [&](int buf) {
        char* base = smem + buf * STG_BYTES;
        for (int i = 0; i < 2; i++) {
            int c = tid + 256 * i;
            int r = c >> 2;
            int kk = (c & 3) * 8;
            *(uint4*)(base + STG_AHI + r * 80 + kk * 2) = stAh[i];
            *(uint4*)(base + STG_ALO + r * 80 + kk * 2) = stAl[i];
        }
        int r = tid >> 2;
        int kk = (tid & 3) * 8;
        *(uint4*)(base + STG_BHI + r * 80 + kk * 2) = stBh;
        *(uint4*)(base + STG_BLO + r * 80 + kk * 2) = stBl;
    };

    auto compute_chunk = [&](int buf) {
        char* base = smem + buf * STG_BYTES;
        for (int ks = 0; ks < 2; ks++) {
            int colOff = ks * 16 + ((lane >> 4) << 3);
            int rsel = lane & 15;
            u32 Ah[2][4];
            u32 Al[2][4];
            u32 Bh[4][2];
            u32 Bl[4][2];
            for (int mf = 0; mf < 2; mf++) {
                int row = wm * 32 + mf * 16 + rsel;
                ldsm4(Ah[mf], base + STG_AHI + row * 80 + colOff * 2);
                ldsm4(Al[mf], base + STG_ALO + row * 80 + colOff * 2);
            }
            for (int p = 0; p < 2; p++) {
                int row = wn * 32 + p * 16 + rsel;
                u32 t[4];
                ldsm4(t, base + STG_BHI + row * 80 + colOff * 2);
                Bh[2 * p][0] = t[0];
                Bh[2 * p][1] = t[2];
                Bh[2 * p + 1][0] = t[1];
                Bh[2 * p + 1][1] = t[3];
                ldsm4(t, base + STG_BLO + row * 80 + colOff * 2);
                Bl[2 * p][0] = t[0];
                Bl[2 * p][1] = t[2];
                Bl[2 * p + 1][0] = t[1];
                Bl[2 * p + 1][1] = t[3];
            }
            for (int mf = 0; mf < 2; mf++) {
                for (int nf = 0; nf < 4; nf++) {
                    mma16816(acc[mf][nf], Ah[mf], Bh[nf]);
                    mma16816(acc[mf][nf], Ah[mf], Bl[nf]);
                    mma16816(acc[mf][nf], Al[mf], Bh[nf]);
                }
            }
        }
    };

    load_chunk(0);
    store_chunk(0);
    __syncthreads();
    for (int kc = 0; kc < KCH; kc++) {
        if (kc + 1 < KCH) { load_chunk(kc + 1); }
        compute_chunk(kc & 1);
        __syncthreads();
        if (kc + 1 < KCH) {
            store_chunk((kc + 1) & 1);
            __syncthreads();
        }
    }

    for (int mf = 0; mf < 2; mf++) {
        int r0 = m0 + wm * 32 + mf * 16 + (lane >> 2);
        for (int nf = 0; nf < 4; nf++) {
            int cb = n0 + wn * 32 + nf * 8 + (lane & 3) * 2;
            if (r0 < M) {
                float2 v;
                v.x = acc[mf][nf][0];
                v.y = acc[mf][nf][1];
                *(float2*)&C[(size_t)r0 * ldn + cb] = v;
            }
            if (r0 + 8 < M) {
                float2 v;
                v.x = acc[mf][nf][2];
                v.y = acc[mf][nf][3];
                *(float2*)&C[(size_t)(r0 + 8) * ldn + cb] = v;
            }
        }
    }

    if (DOTS) {
        int head = n0 >> 6;  // cols [0,64) = mu head, [64,128) = ls head
        for (int mf = 0; mf < 2; mf++) {
            float sA0 = 0.0f;
            float sD0 = 0.0f;
            float sA1 = 0.0f;
            float sD1 = 0.0f;
            for (int nf = 0; nf < 4; nf++) {
                int cb = n0 + wn * 32 + nf * 8 + (lane & 3) * 2;
                float s0v = Sv[cb];
                float s1v = Sv[cb + 1];
                float d0v = Dv[cb];
                float d1v = Dv[cb + 1];
                sA0 += acc[mf][nf][0] * s0v + acc[mf][nf][1] * s1v;
                sD0 += acc[mf][nf][0] * d0v + acc[mf][nf][1] * d1v;
                sA1 += acc[mf][nf][2] * s0v + acc[mf][nf][3] * s1v;
                sD1 += acc[mf][nf][2] * d0v + acc[mf][nf][3] * d1v;
            }
            for (int o = 1; o < 4; o <<= 1) {
                sA0 += __shfl_xor_sync(0xffffffffu, sA0, o);
                sD0 += __shfl_xor_sync(0xffffffffu, sD0, o);
                sA1 += __shfl_xor_sync(0xffffffffu, sA1, o);
                sD1 += __shfl_xor_sync(0xffffffffu, sD1, o);
            }
            if ((lane & 3) == 0) {
                int r0 = m0 + wm * 32 + mf * 16 + (lane >> 2);
                if (r0 < M) {
                    atomicAdd(&asrc[2 * r0 + head], sA0);
                    atomicAdd(&adst[2 * r0 + head], sD0);
                }
                if (r0 + 8 < M) {
                    atomicAdd(&asrc[2 * (r0 + 8) + head], sA1);
                    atomicAdd(&adst[2 * (r0 + 8) + head], sD1);
                }
            }
        }
    }
}

// ---------------- layer-1 dots from x via folded WA1 -------------------------
__global__ void dots_x_kernel(const float* __restrict__ x,
                              const float* __restrict__ WA,
                              float* __restrict__ asrc,
                              float* __restrict__ adst,
                              int n_nodes)
{
    int w = (blockIdx.x * blockDim.x + threadIdx.x) >> 5;
    int lane = threadIdx.x & 31;
    if (w >= n_nodes) { return; }
    const float* xp = x + (size_t)w * 128;
    float4 xv = *(const float4*)(xp + lane * 4);
    float xs[4];
    xs[0] = xv.x; xs[1] = xv.y; xs[2] = xv.z; xs[3] = xv.w;
    float a0 = 0.0f;
    float a1 = 0.0f;
    float a2 = 0.0f;
    float a3 = 0.0f;
    for (int q = 0; q < 4; q++) {
        float4 wv = *(const float4*)(WA + (size_t)(lane * 4 + q) * 4);
        a0 += xs[q] * wv.x;
        a1 += xs[q] * wv.y;
        a2 += xs[q] * wv.z;
        a3 += xs[q] * wv.w;
    }
    for (int o = 16; o > 0; o >>= 1) {
        a0 += __shfl_xor_sync(0xffffffffu, a0, o);
        a1 += __shfl_xor_sync(0xffffffffu, a1, o);
        a2 += __shfl_xor_sync(0xffffffffu, a2, o);
        a3 += __shfl_xor_sync(0xffffffffu, a3, o);
    }
    if (lane == 0) {
        asrc[2 * w] = a0;
        asrc[2 * w + 1] = a1;
        adst[2 * w] = a2;
        adst[2 * w + 1] = a3;
    }
}

__device__ __forceinline__ float lrelu(float x)
{
    return (x > 0.0f) ? x : 0.2f * x;
}

__device__ __forceinline__ void online_upd(float e, float& m, float& s)
{
    if (e > m) {
        s = s * __expf(m - e) + 1.0f;
        m = e;
    } else {
        s += __expf(e - m);
    }
}

// ---------------- layer-1 aggregation (ELU + bf16 split out) -----------------
__global__ void gat_agg_l1_kernel(const float* __restrict__ asrc,
                                  const float* __restrict__ adst,
                                  const float* __restrict__ h,
                                  const float* __restrict__ bias,
                                  __nv_bfloat16* __restrict__ ohi,
                                  __nv_bfloat16* __restrict__ olo,
                                  int n_nodes)
{
    int w = (blockIdx.x * blockDim.x + threadIdx.x) >> 5;
    int lane = threadIdx.x & 31;
    if (w >= n_nodes) { return; }
    int s0 = g_off[w];
    int s1 = g_off[w + 1];
    float ad0 = adst[2 * w];
    float ad1 = adst[2 * w + 1];

    float m0 = -1e30f;
    float m1 = -1e30f;
    float sm0 = 0.0f;
    float sm1 = 0.0f;
    for (int i = s0 + lane; i < s1; i += 32) {
        int s = g_srcList[i];
        float e0 = lrelu(asrc[2 * s] + ad0);
        float e1 = lrelu(asrc[2 * s + 1] + ad1);
        online_upd(e0, m0, sm0);
        online_upd(e1, m1, sm1);
    }
    float M0 = m0;
    float M1 = m1;
    for (int o = 16; o > 0; o >>= 1) {
        M0 = fmaxf(M0, __shfl_xor_sync(0xffffffffu, M0, o));
        M1 = fmaxf(M1, __shfl_xor_sync(0xffffffffu, M1, o));
    }
    float t0 = sm0 * __expf(m0 - M0);
    float t1 = sm1 * __expf(m1 - M1);
    for (int o = 16; o > 0; o >>= 1) {
        t0 += __shfl_xor_sync(0xffffffffu, t0, o);
        t1 += __shfl_xor_sync(0xffffffffu, t1, o);
    }
    float inv0 = 1.0f / (t0 + 1e-16f);
    float inv1 = 1.0f / (t1 + 1e-16f);
    m0 = M0;
    m1 = M1;

    float acc0[4];
    float acc1[4];
    for (int v = 0; v < 4; v++) { acc0[v] = 0.0f; acc1[v] = 0.0f; }
    int i = s0;
    for (; i + 2 <= s1; i += 2) {
        int sa = g_srcList[i];
        int sb = g_srcList[i + 1];
        float wa0 = __expf(lrelu(asrc[2 * sa] + ad0) - m0) * inv0;
        float wa1 = __expf(lrelu(asrc[2 * sa + 1] + ad1) - m1) * inv1;
        float wb0 = __expf(lrelu(asrc[2 * sb] + ad0) - m0) * inv0;
        float wb1 = __expf(lrelu(asrc[2 * sb + 1] + ad1) - m1) * inv1;
        const float* ha = h + (size_t)sa * 256;
        const float* hb = h + (size_t)sb * 256;
        float4 a0 = *(const float4*)(ha + lane * 4);
        float4 a1 = *(const float4*)(ha + 128 + lane * 4);
        float4 b0 = *(const float4*)(hb + lane * 4);
        float4 b1 = *(const float4*)(hb + 128 + lane * 4);
        acc0[0] += wa0 * a0.x + wb0 * b0.x;
        acc0[1] += wa0 * a0.y + wb0 * b0.y;
        acc0[2] += wa0 * a0.z + wb0 * b0.z;
        acc0[3] += wa0 * a0.w + wb0 * b0.w;
        acc1[0] += wa1 * a1.x + wb1 * b1.x;
        acc1[1] += wa1 * a1.y + wb1 * b1.y;
        acc1[2] += wa1 * a1.z + wb1 * b1.z;
        acc1[3] += wa1 * a1.w + wb1 * b1.w;
    }
    if (i < s1) {
        int sa = g_srcList[i];
        float wa0 = __expf(lrelu(asrc[2 * sa] + ad0) - m0) * inv0;
        float wa1 = __expf(lrelu(asrc[2 * sa + 1] + ad1) - m1) * inv1;
        const float* ha = h + (size_t)sa * 256;
        float4 a0 = *(const float4*)(ha + lane * 4);
        float4 a1 = *(const float4*)(ha + 128 + lane * 4);
        acc0[0] += wa0 * a0.x;
        acc0[1] += wa0 * a0.y;
        acc0[2] += wa0 * a0.z;
        acc0[3] += wa0 * a0.w;
        acc1[0] += wa1 * a1.x;
        acc1[1] += wa1 * a1.y;
        acc1[2] += wa1 * a1.z;
        acc1[3] += wa1 * a1.w;
    }

    size_t base = (size_t)w * 256;
    for (int v = 0; v < 4; v++) {
        int c0 = lane * 4 + v;
        float r0 = acc0[v] + bias[c0];
        float r1 = acc1[v] + bias[128 + c0];
        r0 = (r0 > 0.0f) ? r0 : expm1f(r0);
        r1 = (r1 > 0.0f) ? r1 : expm1f(r1);
        __nv_bfloat16 h0 = __float2bfloat16(r0);
        __nv_bfloat16 h1 = __float2bfloat16(r1);
        ohi[base + c0] = h0;
        olo[base + c0] = __float2bfloat16(r0 - __bfloat162float(h0));
        ohi[base + 128 + c0] = h1;
        olo[base + 128 + c0] = __float2bfloat16(r1 - __bfloat162float(h1));
    }
}

// ---------------- layer-2 aggregation (mu | logstd, fp32 out) ----------------
__global__ void gat_agg_l2_kernel(const float* __restrict__ asrc,
                                  const float* __restrict__ adst,
                                  const float* __restrict__ h,
                                  const float* __restrict__ bmu,
                                  const float* __restrict__ bls,
                                  float* __restrict__ out_mu,
                                  float* __restrict__ out_ls,
                                  int n_nodes)
{
    int w = (blockIdx.x * blockDim.x + threadIdx.x) >> 5;
    int lane = threadIdx.x & 31;
    if (w >= n_nodes) { return; }
    int s0 = g_off[w];
    int s1 = g_off[w + 1];
    float ad0 = adst[2 * w];
    float ad1 = adst[2 * w + 1];

    float m0 = -1e30f;
    float m1 = -1e30f;
    float sm0 = 0.0f;
    float sm1 = 0.0f;
    for (int i = s0 + lane; i < s1; i += 32) {
        int s = g_srcList[i];
        float e0 = lrelu(asrc[2 * s] + ad0);
        float e1 = lrelu(asrc[2 * s + 1] + ad1);
        online_upd(e0, m0, sm0);
        online_upd(e1, m1, sm1);
    }
    float M0 = m0;
    float M1 = m1;
    for (int o = 16; o > 0; o >>= 1) {
        M0 = fmaxf(M0, __shfl_xor_sync(0xffffffffu, M0, o));
        M1 = fmaxf(M1, __shfl_xor_sync(0xffffffffu, M1, o));
    }
    float t0 = sm0 * __expf(m0 - M0);
    float t1 = sm1 * __expf(m1 - M1);
    for (int o = 16; o > 0; o >>= 1) {
        t0 += __shfl_xor_sync(0xffffffffu, t0, o);
        t1 += __shfl_xor_sync(0xffffffffu, t1, o);
    }
    float inv0 = 1.0f / (t0 + 1e-16f);
    float inv1 = 1.0f / (t1 + 1e-16f);
    m0 = M0;
    m1 = M1;

    float a00 = 0.0f;
    float a01 = 0.0f;
    float a10 = 0.0f;
    float a11 = 0.0f;
    int i = s0;
    for (; i + 2 <= s1; i += 2) {
        int sa = g_srcList[i];
        int sb = g_srcList[i + 1];
        float wa0 = __expf(lrelu(asrc[2 * sa] + ad0) - m0) * inv0;
        float wa1 = __expf(lrelu(asrc[2 * sa + 1] + ad1) - m1) * inv1;
        float wb0 = __expf(lrelu(asrc[2 * sb] + ad0) - m0) * inv0;
        float wb1 = __expf(lrelu(asrc[2 * sb + 1] + ad1) - m1) * inv1;
        const float* ha = h + (size_t)sa * 128;
        const float* hb = h + (size_t)sb * 128;
        float2 va0 = *(const float2*)(ha + lane * 2);
        float2 va1 = *(const float2*)(ha + 64 + lane * 2);
        float2 vb0 = *(const float2*)(hb + lane * 2);
        float2 vb1 = *(const float2*)(hb + 64 + lane * 2);
        a00 += wa0 * va0.x + wb0 * vb0.x;
        a01 += wa0 * va0.y + wb0 * vb0.y;
        a10 += wa1 * va1.x + wb1 * vb1.x;
        a11 += wa1 * va1.y + wb1 * vb1.y;
    }
    if (i < s1) {
        int sa = g_srcList[i];
        float wa0 = __expf(lrelu(asrc[2 * sa] + ad0) - m0) * inv0;
        float wa1 = __expf(lrelu(asrc[2 * sa + 1] + ad1) - m1) * inv1;
        const float* ha = h + (size_t)sa * 128;
        float2 va0 = *(const float2*)(ha + lane * 2);
        float2 va1 = *(const float2*)(ha + 64 + lane * 2);
        a00 += wa0 * va0.x;
        a01 += wa0 * va0.y;
        a10 += wa1 * va1.x;
        a11 += wa1 * va1.y;
    }
    float* o0 = out_mu + (size_t)w * 64 + lane * 2;
    float* o1 = out_ls + (size_t)w * 64 + lane * 2;
    o0[0] = a00 + bmu[lane * 2];
    o0[1] = a01 + bmu[lane * 2 + 1];
    o1[0] = a10 + bls[lane * 2];
    o1[1] = a11 + bls[lane * 2 + 1];
}

// ---------------- host launch ------------------------------------------------
static void* symaddr(const void* s)
{
    void* p = nullptr;
    cudaGetSymbolAddress(&p, s);
    return p;
}

extern "C" void kernel_launch(void* const* d_in, const int* in_sizes, int n_in,
                              void* d_out, int out_size)
{
    const float* x      = (const float*)d_in[0];
    const int*   ei     = (const int*)d_in[1];
    const float* W1     = (const float*)d_in[2];
    const float* attS1  = (const float*)d_in[3];
    const float* attD1  = (const float*)d_in[4];
    const float* b1     = (const float*)d_in[5];
    const float* Wmu    = (const float*)d_in[6];
    const float* attSmu = (const float*)d_in[7];
    const float* attDmu = (const float*)d_in[8];
    const float* bmu    = (const float*)d_in[9];
    const float* Wls    = (const float*)d_in[10];
    const float* attSls = (const float*)d_in[11];
    const float* attDls = (const float*)d_in[12];
    const float* bls    = (const float*)d_in[13];
    float* out = (float*)d_out;

    float* H1 = (float*)symaddr(g_H1);
    float* H2 = (float*)symaddr(g_H2);
    __nv_bfloat16* O1hi  = (__nv_bfloat16*)symaddr(g_O1hi);
    __nv_bfloat16* O1lo  = (__nv_bfloat16*)symaddr(g_O1lo);
    __nv_bfloat16* B1thi = (__nv_bfloat16*)symaddr(g_B1thi);
    __nv_bfloat16* B1tlo = (__nv_bfloat16*)symaddr(g_B1tlo);
    __nv_bfloat16* B2thi = (__nv_bfloat16*)symaddr(g_B2thi);
    __nv_bfloat16* B2tlo = (__nv_bfloat16*)symaddr(g_B2tlo);
    float* WA1 = (float*)symaddr(g_WA1);
    float* as1 = (float*)symaddr(g_as1);
    float* ad1 = (float*)symaddr(g_ad1);
    float* as2 = (float*)symaddr(g_as2);
    float* ad2 = (float*)symaddr(g_ad2);
    int* deg  = (int*)symaddr(g_deg);
    int* off  = (int*)symaddr(g_off);
    int* cur  = (int*)symaddr(g_cur);
    int* srcL = (int*)symaddr(g_srcList);
    float* S2 = (float*)symaddr(g_attS2);
    float* D2 = (float*)symaddr(g_attD2);

    const int N = NNODES;
    const int warpBlocks = (N * 32 + 255) / 256;
    const int mtiles = (N + 127) / 128;  // 391

    cudaFuncSetAttribute(gemm_mma_kernel<4, true, false>,
                         cudaFuncAttributeMaxDynamicSharedMemorySize, GEMM_SMEM);
    cudaFuncSetAttribute(gemm_mma_kernel<8, false, true>,
                         cudaFuncAttributeMaxDynamicSharedMemorySize, GEMM_SMEM);

    // launches 1..3: prep (gemm1 lands at profiled slot 4)
    packW1_kernel<<<(256 * 128 + 255) / 256, 256>>>(W1, B1thi, B1tlo);
    packW2_kernel<<<(128 * 256 + 255) / 256, 256>>>(Wmu, Wls, B2thi, B2tlo);
    prep_misc_kernel<<<3 + (N * 2 + 255) / 256, 256>>>(
        W1, attS1, attD1, attSmu, attSls, attDmu, attDls,
        WA1, S2, D2, as2, ad2);

    // launch 4: layer-1 GEMM: H1 = x @ W1 (N=256 -> 4 col-tiles)
    gemm_mma_kernel<4, true, false><<<dim3(4, mtiles), 256, GEMM_SMEM>>>(
        x, (const __nv_bfloat16*)0, (const __nv_bfloat16*)0,
        B1thi, B1tlo, H1, N, 256,
        (const float*)0, (const float*)0, (float*)0, (float*)0);

    // layer-1 logits
    dots_x_kernel<<<warpBlocks, 256>>>(x, WA1, as1, ad1, N);

    // CSR build
    zero_int_kernel<<<(N + 1 + 255) / 256, 256>>>(deg, N + 1);
    hist_kernel<<<(E_TOT + 255) / 256, 256>>>(ei, deg);
    scan_kernel<<<1, 1024>>>(deg, off, cur, N, E_TOT);
    scatter_kernel<<<(E_TOT + 255) / 256, 256>>>(ei, cur, srcL);

    gat_agg_l1_kernel<<<warpBlocks, 256>>>(as1, ad1, H1, b1, O1hi, O1lo, N);

    // layer-2 GEMM with fused attention dots (atomic partials into as2/ad2)
    gemm_mma_kernel<8, false, true><<<dim3(2, mtiles), 256, GEMM_SMEM>>>(
        (const float*)0, O1hi, O1lo, B2thi, B2tlo, H2, N, 128,
        S2, D2, as2, ad2);

    gat_agg_l2_kernel<<<warpBlocks, 256>>>(as2, ad2, H2, bmu, bls,
                                           out, out + (size_t)N * 64, N);
}

// round 13
// speedup vs baseline: 1.3995x; 1.0958x over previous
#include <cuda_runtime.h>
#include <cuda_bf16.h>
#include <stdint.h>
#include <math.h>

#define NNODES 50000
#define INCH   128
#define E_REAL 400000
#define E_TOT  450000

typedef unsigned int u32;

// ---------------- scratch (device globals) ----------------------------------
__device__ __align__(16) float g_H1[(size_t)NNODES * 256];
__device__ __align__(16) float g_H2[(size_t)NNODES * 128];
__device__ __align__(16) __nv_bfloat16 g_xhi[(size_t)NNODES * 128];
__device__ __align__(16) __nv_bfloat16 g_xlo[(size_t)NNODES * 128];
__device__ __align__(16) __nv_bfloat16 g_O1hi[(size_t)NNODES * 256];
__device__ __align__(16) __nv_bfloat16 g_O1lo[(size_t)NNODES * 256];
__device__ __align__(16) __nv_bfloat16 g_B1thi[256 * 128];
__device__ __align__(16) __nv_bfloat16 g_B1tlo[256 * 128];
__device__ __align__(16) __nv_bfloat16 g_B2thi[128 * 256];
__device__ __align__(16) __nv_bfloat16 g_B2tlo[128 * 256];
__device__ __align__(16) float g_WA1[128 * 4];
__device__ float g_as1[NNODES * 2];
__device__ float g_ad1[NNODES * 2];
__device__ float g_as2[NNODES * 2];
__device__ float g_ad2[NNODES * 2];
__device__ int   g_deg[NNODES + 1];
__device__ int   g_off[NNODES + 1];
__device__ int   g_cur[NNODES];
__device__ int   g_srcList[E_TOT];
__device__ float g_attS2[128];
__device__ float g_attD2[128];

// ---------------- small utility kernels -------------------------------------
__global__ void zero_int_kernel(int* p, int n)
{
    int i = blockIdx.x * blockDim.x + threadIdx.x;
    if (i < n) { p[i] = 0; }
}

__global__ void hist_kernel(const int* __restrict__ ei, int* __restrict__ deg)
{
    int i = blockIdx.x * blockDim.x + threadIdx.x;
    if (i >= E_TOT) { return; }
    int dst = (i < E_REAL) ? ei[E_REAL + i] : (i - E_REAL);
    atomicAdd(&deg[dst], 1);
}

__global__ void scan_kernel(const int* __restrict__ deg, int* __restrict__ off,
                            int* __restrict__ cur, int n, int total)
{
    __shared__ int warpSums[32];
    __shared__ int s_carry;
    int tid = threadIdx.x;
    int lane = tid & 31;
    int wid = tid >> 5;
    if (tid == 0) { s_carry = 0; }
    __syncthreads();
    for (int base = 0; base < n; base += 1024) {
        int idx = base + tid;
        int v = (idx < n) ? deg[idx] : 0;
        int x = v;
        for (int o = 1; o < 32; o <<= 1) {
            int y = __shfl_up_sync(0xffffffffu, x, o);
            if (lane >= o) { x += y; }
        }
        if (lane == 31) { warpSums[wid] = x; }
        __syncthreads();
        if (wid == 0) {
            int w = warpSums[lane];
            for (int o = 1; o < 32; o <<= 1) {
                int y = __shfl_up_sync(0xffffffffu, w, o);
                if (lane >= o) { w += y; }
            }
            warpSums[lane] = w;
        }
        __syncthreads();
        int blockIncl = x + ((wid > 0) ? warpSums[wid - 1] : 0);
        int excl = blockIncl - v;
        if (idx < n) {
            int val = s_carry + excl;
            off[idx] = val;
            cur[idx] = val;
        }
        __syncthreads();
        if (tid == 1023) { s_carry += blockIncl; }
        __syncthreads();
    }
    if (tid == 0) { off[n] = total; }
}

__global__ void scatter_kernel(const int* __restrict__ ei, int* __restrict__ cur,
                               int* __restrict__ srcList)
{
    int i = blockIdx.x * blockDim.x + threadIdx.x;
    if (i >= E_TOT) { return; }
    int src;
    int dst;
    if (i < E_REAL) { src = ei[i]; dst = ei[E_REAL + i]; }
    else            { src = i - E_REAL; dst = src; }
    int p = atomicAdd(&cur[dst], 1);
    srcList[p] = src;
}

// blocks 0-1: fold WA1; block 2: pack att2; blocks 3+: split x into bf16 hi/lo
__global__ void prep_misc_kernel(const float* __restrict__ W1,
                                 const float* __restrict__ attS1,
                                 const float* __restrict__ attD1,
                                 const float* __restrict__ smu,
                                 const float* __restrict__ sls,
                                 const float* __restrict__ dmu,
                                 const float* __restrict__ dls,
                                 const float* __restrict__ x,
                                 float* __restrict__ WA,
                                 float* __restrict__ S,
                                 float* __restrict__ D,
                                 __nv_bfloat16* __restrict__ xhi,
                                 __nv_bfloat16* __restrict__ xlo)
{
    int b = blockIdx.x;
    int t = threadIdx.x;
    if (b < 2) {
        int it = b * 256 + t;      // 0..511
        int k = it >> 2;
        int j = it & 3;
        int h = j & 1;
        const float* av = (j < 2) ? attS1 : attD1;
        float s = 0.0f;
        for (int c = 0; c < 128; c++) {
            s += W1[k * 256 + h * 128 + c] * av[h * 128 + c];
        }
        WA[k * 4 + j] = s;
    } else if (b == 2) {
        if (t < 64) {
            S[t] = smu[t];
            S[64 + t] = sls[t];
            D[t] = dmu[t];
            D[64 + t] = dls[t];
        }
    } else {
        int i = (b - 3) * 256 + t;
        if (i < NNODES * 128) {
            float v = x[i];
            __nv_bfloat16 h = __float2bfloat16(v);
            xhi[i] = h;
            xlo[i] = __float2bfloat16(v - __bfloat162float(h));
        }
    }
}

__global__ void packW1_kernel(const float* __restrict__ W1,
                              __nv_bfloat16* __restrict__ hi,
                              __nv_bfloat16* __restrict__ lo)
{
    int i = blockIdx.x * blockDim.x + threadIdx.x;
    if (i >= 256 * 128) { return; }
    int nn = i >> 7;
    int kk = i & 127;
    float v = W1[kk * 256 + nn];
    __nv_bfloat16 h = __float2bfloat16(v);
    hi[i] = h;
    lo[i] = __float2bfloat16(v - __bfloat162float(h));
}

__global__ void packW2_kernel(const float* __restrict__ Wmu,
                              const float* __restrict__ Wls,
                              __nv_bfloat16* __restrict__ hi,
                              __nv_bfloat16* __restrict__ lo)
{
    int i = blockIdx.x * blockDim.x + threadIdx.x;
    if (i >= 128 * 256) { return; }
    int nn = i >> 8;
    int kk = i & 255;
    float v = (nn < 64) ? Wmu[kk * 64 + nn] : Wls[kk * 64 + (nn - 64)];
    __nv_bfloat16 h = __float2bfloat16(v);
    hi[i] = h;
    lo[i] = __float2bfloat16(v - __bfloat162float(h));
}

// ---------------- mma.sync / cp.async helpers --------------------------------
__device__ __forceinline__ u32 smem_u32(const void* p)
{
    u32 a;
    asm("{ .reg .u64 t; cvta.to.shared.u64 t, %1; cvt.u32.u64 %0, t; }"
        : "=r"(a) : "l"(p));
    return a;
}

__device__ __forceinline__ void ldsm4(u32* r, u32 addr)
{
    asm volatile("ldmatrix.sync.aligned.m8n8.x4.shared.b16 {%0,%1,%2,%3}, [%4];"
        : "=r"(r[0]), "=r"(r[1]), "=r"(r[2]), "=r"(r[3]) : "r"(addr));
}

__device__ __forceinline__ void mma16816(float* c, const u32* a, const u32* b)
{
    asm volatile("mma.sync.aligned.m16n8k16.row.col.f32.bf16.bf16.f32 "
        "{%0,%1,%2,%3}, {%4,%5,%6,%7}, {%8,%9}, {%0,%1,%2,%3};"
        : "+f"(c[0]), "+f"(c[1]), "+f"(c[2]), "+f"(c[3])
        : "r"(a[0]), "r"(a[1]), "r"(a[2]), "r"(a[3]), "r"(b[0]), "r"(b[1]));
}

__device__ __forceinline__ void cpa16(u32 dst, const void* src, int szbytes)
{
    asm volatile("cp.async.cg.shared.global [%0], [%1], 16, %2;"
        :: "r"(dst), "l"(src), "r"(szbytes));
}

__device__ __forceinline__ void cpa_commit()
{
    asm volatile("cp.async.commit_group;");
}

template <int NN>
__device__ __forceinline__ void cpa_wait()
{
    asm volatile("cp.async.wait_group %0;" :: "n"(NN));
}

// smem stage (bytes): A_hi[128][40] | A_lo | B_hi[128][40] | B_lo  (pitch 80B)
#define STG_AHI 0
#define STG_ALO 10240
#define STG_BHI 20480
#define STG_BLO 30720
#define STG_BYTES 40960
#define GEMM_SMEM (2 * STG_BYTES)

// ---------------- pipelined bf16x3 mma.sync GEMM (128x128 CTA tile) ----------
// C[M x ldn]; CTA: rows [m0,m0+128), cols [n0,n0+128). KCH 32-wide K chunks.
// A, Bt as bf16 hi/lo; Bt: [ldn rows][KTOT], K contiguous.
// DOTS: write attention-dot partials (ldn==128, grid.x==1; head = wn).
template <int KCH, bool DOTS>
__global__ __launch_bounds__(256, 2)
void gemm_mma_kernel(const __nv_bfloat16* __restrict__ Ahi,
                     const __nv_bfloat16* __restrict__ Alo,
                     const __nv_bfloat16* __restrict__ Bthi,
                     const __nv_bfloat16* __restrict__ Btlo,
                     float* __restrict__ C, int M, int ldn,
                     const float* __restrict__ Sv,
                     const float* __restrict__ Dv,
                     float* __restrict__ dotS,
                     float* __restrict__ dotD)
{
    extern __shared__ char smem[];
    const int KTOT = KCH * 32;
    u32 sb = smem_u32(smem);
    int tid = threadIdx.x;
    int warp = tid >> 5;
    int lane = tid & 31;
    int wm = warp >> 1;                 // 0..3 (32-row slabs)
    int wn = warp & 1;                  // 0..1 (64-col slabs)
    int m0 = blockIdx.y * 128;
    int n0 = blockIdx.x * 128;

    float acc[2][8][4];
    for (int a = 0; a < 2; a++) {
        for (int b = 0; b < 8; b++) {
            for (int c = 0; c < 4; c++) { acc[a][b][c] = 0.0f; }
        }
    }

    auto issue = [&](int kc, int buf) {
        u32 base = sb + buf * STG_BYTES;
        for (int i = 0; i < 2; i++) {
            int c = tid + 256 * i;
            int r = c >> 2;              // 0..127
            int kk = (c & 3) * 8;        // 0,8,16,24
            u32 off = (u32)(r * 80 + kk * 2);
            int grow = m0 + r;
            int gcol = kc * 32 + kk;
            size_t asrc = (size_t)((grow < M) ? grow : 0) * KTOT + gcol;
            int sz = (grow < M) ? 16 : 0;
            cpa16(base + STG_AHI + off, Ahi + asrc, sz);
            cpa16(base + STG_ALO + off, Alo + asrc, sz);
            size_t bsrc = (size_t)(n0 + r) * KTOT + gcol;
            cpa16(base + STG_BHI + off, Bthi + bsrc, 16);
            cpa16(base + STG_BLO + off, Btlo + bsrc, 16);
        }
    };

    auto compute = [&](int buf) {
        u32 base = sb + buf * STG_BYTES;
        for (int ks = 0; ks < 2; ks++) {
            int colOff = ks * 16 + ((lane >> 4) << 3);
            int rsel = lane & 15;
            u32 Ah[2][4];
            u32 Al[2][4];
            u32 Bh[8][2];
            u32 Bl[8][2];
            for (int mf = 0; mf < 2; mf++) {
                int row = wm * 32 + mf * 16 + rsel;
                ldsm4(Ah[mf], base + STG_AHI + row * 80 + colOff * 2);
                ldsm4(Al[mf], base + STG_ALO + row * 80 + colOff * 2);
            }
            for (int p = 0; p < 4; p++) {
                int row = wn * 64 + p * 16 + rsel;
                u32 t[4];
                ldsm4(t, base + STG_BHI + row * 80 + colOff * 2);
                Bh[2 * p][0] = t[0];
                Bh[2 * p][1] = t[2];
                Bh[2 * p + 1][0] = t[1];
                Bh[2 * p + 1][1] = t[3];
                ldsm4(t, base + STG_BLO + row * 80 + colOff * 2);
                Bl[2 * p][0] = t[0];
                Bl[2 * p][1] = t[2];
                Bl[2 * p + 1][0] = t[1];
                Bl[2 * p + 1][1] = t[3];
            }
            for (int mf = 0; mf < 2; mf++) {
                for (int nf = 0; nf < 8; nf++) {
                    mma16816(acc[mf][nf], Ah[mf], Bh[nf]);
                    mma16816(acc[mf][nf], Ah[mf], Bl[nf]);
                    mma16816(acc[mf][nf], Al[mf], Bh[nf]);
                }
            }
        }
    };

    issue(0, 0);
    cpa_commit();
    for (int kc = 0; kc < KCH; kc++) {
        if (kc + 1 < KCH) {
            issue(kc + 1, (kc + 1) & 1);
            cpa_commit();
            cpa_wait<1>();
        } else {
            cpa_wait<0>();
        }
        __syncthreads();
        compute(kc & 1);
        __syncthreads();
    }

    for (int mf = 0; mf < 2; mf++) {
        int r0 = m0 + wm * 32 + mf * 16 + (lane >> 2);
        for (int nf = 0; nf < 8; nf++) {
            int cb = n0 + wn * 64 + nf * 8 + (lane & 3) * 2;
            if (r0 < M) {
                float2 v;
                v.x = acc[mf][nf][0];
                v.y = acc[mf][nf][1];
                *(float2*)&C[(size_t)r0 * ldn + cb] = v;
            }
            if (r0 + 8 < M) {
                float2 v;
                v.x = acc[mf][nf][2];
                v.y = acc[mf][nf][3];
                *(float2*)&C[(size_t)(r0 + 8) * ldn + cb] = v;
            }
        }
    }

    if (DOTS) {
        int head = (n0 + wn * 64) >> 6;
        for (int mf = 0; mf < 2; mf++) {
            float sA0 = 0.0f;
            float sD0 = 0.0f;
            float sA1 = 0.0f;
            float sD1 = 0.0f;
            for (int nf = 0; nf < 8; nf++) {
                int cb = n0 + wn * 64 + nf * 8 + (lane & 3) * 2;
                float s0v = Sv[cb];
                float s1v = Sv[cb + 1];
                float d0v = Dv[cb];
                float d1v = Dv[cb + 1];
                sA0 += acc[mf][nf][0] * s0v + acc[mf][nf][1] * s1v;
                sD0 += acc[mf][nf][0] * d0v + acc[mf][nf][1] * d1v;
                sA1 += acc[mf][nf][2] * s0v + acc[mf][nf][3] * s1v;
                sD1 += acc[mf][nf][2] * d0v + acc[mf][nf][3] * d1v;
            }
            for (int o = 1; o < 4; o <<= 1) {
                sA0 += __shfl_xor_sync(0xffffffffu, sA0, o);
                sD0 += __shfl_xor_sync(0xffffffffu, sD0, o);
                sA1 += __shfl_xor_sync(0xffffffffu, sA1, o);
                sD1 += __shfl_xor_sync(0xffffffffu, sD1, o);
            }
            if ((lane & 3) == 0) {
                int r0 = m0 + wm * 32 + mf * 16 + (lane >> 2);
                if (r0 < M) {
                    dotS[2 * r0 + head] = sA0;
                    dotD[2 * r0 + head] = sD0;
                }
                if (r0 + 8 < M) {
                    dotS[2 * (r0 + 8) + head] = sA1;
                    dotD[2 * (r0 + 8) + head] = sD1;
                }
            }
        }
    }
}

// ---------------- layer-1 dots from x via folded WA1 -------------------------
__global__ void dots_x_kernel(const float* __restrict__ x,
                              const float* __restrict__ WA,
                              float* __restrict__ asrc,
                              float* __restrict__ adst,
                              int n_nodes)
{
    int w = (blockIdx.x * blockDim.x + threadIdx.x) >> 5;
    int lane = threadIdx.x & 31;
    if (w >= n_nodes) { return; }
    const float* xp = x + (size_t)w * 128;
    float4 xv = *(const float4*)(xp + lane * 4);
    float xs[4];
    xs[0] = xv.x; xs[1] = xv.y; xs[2] = xv.z; xs[3] = xv.w;
    float a0 = 0.0f;
    float a1 = 0.0f;
    float a2 = 0.0f;
    float a3 = 0.0f;
    for (int q = 0; q < 4; q++) {
        float4 wv = *(const float4*)(WA + (size_t)(lane * 4 + q) * 4);
        a0 += xs[q] * wv.x;
        a1 += xs[q] * wv.y;
        a2 += xs[q] * wv.z;
        a3 += xs[q] * wv.w;
    }
    for (int o = 16; o > 0; o >>= 1) {
        a0 += __shfl_xor_sync(0xffffffffu, a0, o);
        a1 += __shfl_xor_sync(0xffffffffu, a1, o);
        a2 += __shfl_xor_sync(0xffffffffu, a2, o);
        a3 += __shfl_xor_sync(0xffffffffu, a3, o);
    }
    if (lane == 0) {
        asrc[2 * w] = a0;
        asrc[2 * w + 1] = a1;
        adst[2 * w] = a2;
        adst[2 * w + 1] = a3;
    }
}

__device__ __forceinline__ float lrelu(float x)
{
    return (x > 0.0f) ? x : 0.2f * x;
}

__device__ __forceinline__ void online_upd(float e, float& m, float& s)
{
    if (e > m) {
        s = s * __expf(m - e) + 1.0f;
        m = e;
    } else {
        s += __expf(e - m);
    }
}

// ---------------- layer-1 aggregation (ELU + bf16 split out) -----------------
__global__ void gat_agg_l1_kernel(const float* __restrict__ asrc,
                                  const float* __restrict__ adst,
                                  const float* __restrict__ h,
                                  const float* __restrict__ bias,
                                  __nv_bfloat16* __restrict__ ohi,
                                  __nv_bfloat16* __restrict__ olo,
                                  int n_nodes)
{
    int w = (blockIdx.x * blockDim.x + threadIdx.x) >> 5;
    int lane = threadIdx.x & 31;
    if (w >= n_nodes) { return; }
    int s0 = g_off[w];
    int s1 = g_off[w + 1];
    float ad0 = adst[2 * w];
    float ad1 = adst[2 * w + 1];

    float m0 = -1e30f;
    float m1 = -1e30f;
    float sm0 = 0.0f;
    float sm1 = 0.0f;
    for (int i = s0 + lane; i < s1; i += 32) {
        int s = g_srcList[i];
        float e0 = lrelu(asrc[2 * s] + ad0);
        float e1 = lrelu(asrc[2 * s + 1] + ad1);
        online_upd(e0, m0, sm0);
        online_upd(e1, m1, sm1);
    }
    float M0 = m0;
    float M1 = m1;
    for (int o = 16; o > 0; o >>= 1) {
        M0 = fmaxf(M0, __shfl_xor_sync(0xffffffffu, M0, o));
        M1 = fmaxf(M1, __shfl_xor_sync(0xffffffffu, M1, o));
    }
    float t0 = sm0 * __expf(m0 - M0);
    float t1 = sm1 * __expf(m1 - M1);
    for (int o = 16; o > 0; o >>= 1) {
        t0 += __shfl_xor_sync(0xffffffffu, t0, o);
        t1 += __shfl_xor_sync(0xffffffffu, t1, o);
    }
    float inv0 = 1.0f / (t0 + 1e-16f);
    float inv1 = 1.0f / (t1 + 1e-16f);
    m0 = M0;
    m1 = M1;

    float acc0[4];
    float acc1[4];
    for (int v = 0; v < 4; v++) { acc0[v] = 0.0f; acc1[v] = 0.0f; }
    int i = s0;
    for (; i + 2 <= s1; i += 2) {
        int sa = g_srcList[i];
        int sb = g_srcList[i + 1];
        float wa0 = __expf(lrelu(asrc[2 * sa] + ad0) - m0) * inv0;
        float wa1 = __expf(lrelu(asrc[2 * sa + 1] + ad1) - m1) * inv1;
        float wb0 = __expf(lrelu(asrc[2 * sb] + ad0) - m0) * inv0;
        float wb1 = __expf(lrelu(asrc[2 * sb + 1] + ad1) - m1) * inv1;
        const float* ha = h + (size_t)sa * 256;
        const float* hb = h + (size_t)sb * 256;
        float4 a0 = *(const float4*)(ha + lane * 4);
        float4 a1 = *(const float4*)(ha + 128 + lane * 4);
        float4 b0 = *(const float4*)(hb + lane * 4);
        float4 b1 = *(const float4*)(hb + 128 + lane * 4);
        acc0[0] += wa0 * a0.x + wb0 * b0.x;
        acc0[1] += wa0 * a0.y + wb0 * b0.y;
        acc0[2] += wa0 * a0.z + wb0 * b0.z;
        acc0[3] += wa0 * a0.w + wb0 * b0.w;
        acc1[0] += wa1 * a1.x + wb1 * b1.x;
        acc1[1] += wa1 * a1.y + wb1 * b1.y;
        acc1[2] += wa1 * a1.z + wb1 * b1.z;
        acc1[3] += wa1 * a1.w + wb1 * b1.w;
    }
    if (i < s1) {
        int sa = g_srcList[i];
        float wa0 = __expf(lrelu(asrc[2 * sa] + ad0) - m0) * inv0;
        float wa1 = __expf(lrelu(asrc[2 * sa + 1] + ad1) - m1) * inv1;
        const float* ha = h + (size_t)sa * 256;
        float4 a0 = *(const float4*)(ha + lane * 4);
        float4 a1 = *(const float4*)(ha + 128 + lane * 4);
        acc0[0] += wa0 * a0.x;
        acc0[1] += wa0 * a0.y;
        acc0[2] += wa0 * a0.z;
        acc0[3] += wa0 * a0.w;
        acc1[0] += wa1 * a1.x;
        acc1[1] += wa1 * a1.y;
        acc1[2] += wa1 * a1.z;
        acc1[3] += wa1 * a1.w;
    }

    size_t base = (size_t)w * 256;
    for (int v = 0; v < 4; v++) {
        int c0 = lane * 4 + v;
        float r0 = acc0[v] + bias[c0];
        float r1 = acc1[v] + bias[128 + c0];
        r0 = (r0 > 0.0f) ? r0 : expm1f(r0);
        r1 = (r1 > 0.0f) ? r1 : expm1f(r1);
        __nv_bfloat16 h0 = __float2bfloat16(r0);
        __nv_bfloat16 h1 = __float2bfloat16(r1);
        ohi[base + c0] = h0;
        olo[base + c0] = __float2bfloat16(r0 - __bfloat162float(h0));
        ohi[base + 128 + c0] = h1;
        olo[base + 128 + c0] = __float2bfloat16(r1 - __bfloat162float(h1));
    }
}

// ---------------- layer-2 aggregation (mu | logstd, fp32 out) ----------------
__global__ void gat_agg_l2_kernel(const float* __restrict__ asrc,
                                  const float* __restrict__ adst,
                                  const float* __restrict__ h,
                                  const float* __restrict__ bmu,
                                  const float* __restrict__ bls,
                                  float* __restrict__ out_mu,
                                  float* __restrict__ out_ls,
                                  int n_nodes)
{
    int w = (blockIdx.x * blockDim.x + threadIdx.x) >> 5;
    int lane = threadIdx.x & 31;
    if (w >= n_nodes) { return; }
    int s0 = g_off[w];
    int s1 = g_off[w + 1];
    float ad0 = adst[2 * w];
    float ad1 = adst[2 * w + 1];

    float m0 = -1e30f;
    float m1 = -1e30f;
    float sm0 = 0.0f;
    float sm1 = 0.0f;
    for (int i = s0 + lane; i < s1; i += 32) {
        int s = g_srcList[i];
        float e0 = lrelu(asrc[2 * s] + ad0);
        float e1 = lrelu(asrc[2 * s + 1] + ad1);
        online_upd(e0, m0, sm0);
        online_upd(e1, m1, sm1);
    }
    float M0 = m0;
    float M1 = m1;
    for (int o = 16; o > 0; o >>= 1) {
        M0 = fmaxf(M0, __shfl_xor_sync(0xffffffffu, M0, o));
        M1 = fmaxf(M1, __shfl_xor_sync(0xffffffffu, M1, o));
    }
    float t0 = sm0 * __expf(m0 - M0);
    float t1 = sm1 * __expf(m1 - M1);
    for (int o = 16; o > 0; o >>= 1) {
        t0 += __shfl_xor_sync(0xffffffffu, t0, o);
        t1 += __shfl_xor_sync(0xffffffffu, t1, o);
    }
    float inv0 = 1.0f / (t0 + 1e-16f);
    float inv1 = 1.0f / (t1 + 1e-16f);
    m0 = M0;
    m1 = M1;

    float a00 = 0.0f;
    float a01 = 0.0f;
    float a10 = 0.0f;
    float a11 = 0.0f;
    int i = s0;
    for (; i + 2 <= s1; i += 2) {
        int sa = g_srcList[i];
        int sb = g_srcList[i + 1];
        float wa0 = __expf(lrelu(asrc[2 * sa] + ad0) - m0) * inv0;
        float wa1 = __expf(lrelu(asrc[2 * sa + 1] + ad1) - m1) * inv1;
        float wb0 = __expf(lrelu(asrc[2 * sb] + ad0) - m0) * inv0;
        float wb1 = __expf(lrelu(asrc[2 * sb + 1] + ad1) - m1) * inv1;
        const float* ha = h + (size_t)sa * 128;
        const float* hb = h + (size_t)sb * 128;
        float2 va0 = *(const float2*)(ha + lane * 2);
        float2 va1 = *(const float2*)(ha + 64 + lane * 2);
        float2 vb0 = *(const float2*)(hb + lane * 2);
        float2 vb1 = *(const float2*)(hb + 64 + lane * 2);
        a00 += wa0 * va0.x + wb0 * vb0.x;
        a01 += wa0 * va0.y + wb0 * vb0.y;
        a10 += wa1 * va1.x + wb1 * vb1.x;
        a11 += wa1 * va1.y + wb1 * vb1.y;
    }
    if (i < s1) {
        int sa = g_srcList[i];
        float wa0 = __expf(lrelu(asrc[2 * sa] + ad0) - m0) * inv0;
        float wa1 = __expf(lrelu(asrc[2 * sa + 1] + ad1) - m1) * inv1;
        const float* ha = h + (size_t)sa * 128;
        float2 va0 = *(const float2*)(ha + lane * 2);
        float2 va1 = *(const float2*)(ha + 64 + lane * 2);
        a00 += wa0 * va0.x;
        a01 += wa0 * va0.y;
        a10 += wa1 * va1.x;
        a11 += wa1 * va1.y;
    }
    float* o0 = out_mu + (size_t)w * 64 + lane * 2;
    float* o1 = out_ls + (size_t)w * 64 + lane * 2;
    o0[0] = a00 + bmu[lane * 2];
    o0[1] = a01 + bmu[lane * 2 + 1];
    o1[0] = a10 + bls[lane * 2];
    o1[1] = a11 + bls[lane * 2 + 1];
}

// ---------------- host launch ------------------------------------------------
static void* symaddr(const void* s)
{
    void* p = nullptr;
    cudaGetSymbolAddress(&p, s);
    return p;
}

extern "C" void kernel_launch(void* const* d_in, const int* in_sizes, int n_in,
                              void* d_out, int out_size)
{
    const float* x      = (const float*)d_in[0];
    const int*   ei     = (const int*)d_in[1];
    const float* W1     = (const float*)d_in[2];
    const float* attS1  = (const float*)d_in[3];
    const float* attD1  = (const float*)d_in[4];
    const float* b1     = (const float*)d_in[5];
    const float* Wmu    = (const float*)d_in[6];
    const float* attSmu = (const float*)d_in[7];
    const float* attDmu = (const float*)d_in[8];
    const float* bmu    = (const float*)d_in[9];
    const float* Wls    = (const float*)d_in[10];
    const float* attSls = (const float*)d_in[11];
    const float* attDls = (const float*)d_in[12];
    const float* bls    = (const float*)d_in[13];
    float* out = (float*)d_out;

    float* H1 = (float*)symaddr(g_H1);
    float* H2 = (float*)symaddr(g_H2);
    __nv_bfloat16* xhi   = (__nv_bfloat16*)symaddr(g_xhi);
    __nv_bfloat16* xlo   = (__nv_bfloat16*)symaddr(g_xlo);
    __nv_bfloat16* O1hi  = (__nv_bfloat16*)symaddr(g_O1hi);
    __nv_bfloat16* O1lo  = (__nv_bfloat16*)symaddr(g_O1lo);
    __nv_bfloat16* B1thi = (__nv_bfloat16*)symaddr(g_B1thi);
    __nv_bfloat16* B1tlo = (__nv_bfloat16*)symaddr(g_B1tlo);
    __nv_bfloat16* B2thi = (__nv_bfloat16*)symaddr(g_B2thi);
    __nv_bfloat16* B2tlo = (__nv_bfloat16*)symaddr(g_B2tlo);
    float* WA1 = (float*)symaddr(g_WA1);
    float* as1 = (float*)symaddr(g_as1);
    float* ad1 = (float*)symaddr(g_ad1);
    float* as2 = (float*)symaddr(g_as2);
    float* ad2 = (float*)symaddr(g_ad2);
    int* deg  = (int*)symaddr(g_deg);
    int* off  = (int*)symaddr(g_off);
    int* cur  = (int*)symaddr(g_cur);
    int* srcL = (int*)symaddr(g_srcList);
    float* S2 = (float*)symaddr(g_attS2);
    float* D2 = (float*)symaddr(g_attD2);

    const int N = NNODES;
    const int warpBlocks = (N * 32 + 255) / 256;
    const int mtiles = (N + 127) / 128;  // 391

    cudaFuncSetAttribute(gemm_mma_kernel<4, false>,
                         cudaFuncAttributeMaxDynamicSharedMemorySize, GEMM_SMEM);
    cudaFuncSetAttribute(gemm_mma_kernel<8, true>,
                         cudaFuncAttributeMaxDynamicSharedMemorySize, GEMM_SMEM);

    // launches 1..3: prep (gemm1 lands at profiled slot 4)
    packW1_kernel<<<(256 * 128 + 255) / 256, 256>>>(W1, B1thi, B1tlo);
    packW2_kernel<<<(128 * 256 + 255) / 256, 256>>>(Wmu, Wls, B2thi, B2tlo);
    prep_misc_kernel<<<3 + (N * 128 + 255) / 256, 256>>>(
        W1, attS1, attD1, attSmu, attSls, attDmu, attDls, x,
        WA1, S2, D2, xhi, xlo);

    // launch 4: layer-1 GEMM: H1 = x @ W1 (128x128 tiles; N=256 -> 2 col-tiles)
    gemm_mma_kernel<4, false><<<dim3(2, mtiles), 256, GEMM_SMEM>>>(
        xhi, xlo, B1thi, B1tlo, H1, N, 256,
        (const float*)0, (const float*)0, (float*)0, (float*)0);

    // layer-1 logits
    dots_x_kernel<<<warpBlocks, 256>>>(x, WA1, as1, ad1, N);

    // CSR build
    zero_int_kernel<<<(N + 1 + 255) / 256, 256>>>(deg, N + 1);
    hist_kernel<<<(E_TOT + 255) / 256, 256>>>(ei, deg);
    scan_kernel<<<1, 1024>>>(deg, off, cur, N, E_TOT);
    scatter_kernel<<<(E_TOT + 255) / 256, 256>>>(ei, cur, srcL);

    gat_agg_l1_kernel<<<warpBlocks, 256>>>(as1, ad1, H1, b1, O1hi, O1lo, N);

    // layer-2 GEMM with fused attention dots (plain stores into as2/ad2)
    gemm_mma_kernel<8, true><<<dim3(1, mtiles), 256, GEMM_SMEM>>>(
        O1hi, O1lo, B2thi, B2tlo, H2, N, 128,
        S2, D2, as2, ad2);

    gat_agg_l2_kernel<<<warpBlocks, 256>>>(as2, ad2, H2, bmu, bls,
                                           out, out + (size_t)N * 64, N);
}